// round 1
// baseline (speedup 1.0000x reference)
#include <cuda_runtime.h>
#include <cstdint>
#include <cstddef>

// ---------------- problem constants ----------------
#define TSTEPS 256
#define BB 128      // batch
#define HH 512      // GRU hidden
#define LL 1024     // LSTM hidden
#define VV 1024     // vocab

// ---------------- GEMM tile config ----------------
#define BM 128
#define BN 64
#define BK 32
#define NTH 256
#define APAD 4
#define ASTR (BK + APAD)            // 36 floats per smem row
#define SMEM_BYTES ((2*BM*ASTR + 2*BN*ASTR) * 4)   // 55296
#define CSTR (BN + 4)

// ---------------- persistent device scratch ----------------
__device__ __align__(256) float g_Wg  [2048 * 512];   // GRU combined weights (t>=2), unit-interleaved [r,z,in,hn]
__device__ __align__(256) float g_Wh1 [2048 * 512];   // GRU step-1 weights (x=0 path)
__device__ __align__(256) float g_bg  [2048];         // GRU combined bias (shared by both)
__device__ __align__(256) float g_Wihl[4096 * 512];   // LSTM Wih, unit-interleaved [i,f,g,o]
__device__ __align__(256) float g_bl  [4096];         // LSTM bih+bhh, interleaved
__device__ __align__(256) float g_Whhl[4096 * 1024];  // LSTM Whh, unit-interleaved
__device__ __align__(256) float g_x   [2 * BB * HH];  // GRU state ping-pong
__device__ __align__(256) float g_seq [TSTEPS * BB * HH];          // relu(x_t), 64MB
__device__ __align__(256) float g_Xg  [(size_t)TSTEPS * BB * 4096];// LSTM input gates (+bias), 512MB
__device__ __align__(256) float g_h   [2 * BB * LL];  // LSTM h ping-pong
__device__ __align__(256) float g_c   [BB * LL];      // LSTM c
__device__ __align__(256) float g_hs  [(size_t)TSTEPS * BB * LL];  // LSTM outputs [T,B,L], 128MB

// ---------------- helpers ----------------
__device__ __forceinline__ float tf32r(float x) {
    uint32_t u;
    asm("cvt.rna.tf32.f32 %0, %1;" : "=r"(u) : "f"(x));
    return __uint_as_float(u);
}

__device__ __forceinline__ void mma_tf32(float4& d,
                                         uint32_t a0, uint32_t a1, uint32_t a2, uint32_t a3,
                                         uint32_t b0, uint32_t b1) {
    asm volatile(
        "mma.sync.aligned.m16n8k8.row.col.f32.tf32.tf32.f32 "
        "{%0,%1,%2,%3}, {%4,%5,%6,%7}, {%8,%9}, {%0,%1,%2,%3};\n"
        : "+f"(d.x), "+f"(d.y), "+f"(d.z), "+f"(d.w)
        : "r"(a0), "r"(a1), "r"(a2), "r"(a3), "r"(b0), "r"(b1));
}

__device__ __forceinline__ float sigf(float x) { return 1.0f / (1.0f + expf(-x)); }

enum { EPI_GRU = 0, EPI_LSTM = 1, EPI_XG = 2, EPI_FC = 3 };

// ---------------- unified tiled GEMM (C[BMxBN] = A[BM,K] * W[BN,K]^T) ----------------
// A row-major [M,K]; W row-major [N,K] (weight rows = output columns).
// tf32 mma.sync m16n8k8, fp32 accumulate, double-buffered smem, fused epilogues.
template <int EPI>
__global__ void __launch_bounds__(NTH)
gemm_kernel(const float* __restrict__ A, const float* __restrict__ W,
            const float* __restrict__ bias, int K, int t,
            float* __restrict__ out1, float* __restrict__ out2) {
    extern __shared__ float sm[];
    float* As = sm;                      // [2][BM][ASTR]
    float* Bs = sm + 2 * BM * ASTR;      // [2][BN][ASTR]
    float* Cs = sm;                      // [BM][CSTR]  (reuses As/Bs after mainloop)

    const int tid  = threadIdx.x;
    const int lane = tid & 31;
    const int wid  = tid >> 5;
    const int wm   = wid & 3;   // warp row (0..3): 32 rows each
    const int wn   = wid >> 2;  // warp col (0..1): 32 cols each
    const int n0   = blockIdx.x * BN;
    const int m0   = (EPI == EPI_XG || EPI == EPI_FC) ? (int)blockIdx.y * BM : 0;

    const float* Ab = A + (size_t)m0 * K;
    const float* Wb = W + (size_t)n0 * K;
    const int rA = tid >> 3;          // 0..31
    const int c4 = (tid & 7) * 4;     // 0,4,..,28

    float4 acc[2][4];
#pragma unroll
    for (int mi = 0; mi < 2; mi++)
#pragma unroll
        for (int ni = 0; ni < 4; ni++) acc[mi][ni] = make_float4(0.f, 0.f, 0.f, 0.f);

    float4 ra[4], rb2[2];
    const int nk = K >> 5;

    // prologue: tile 0 -> smem buf 0
#pragma unroll
    for (int i = 0; i < 4; i++) ra[i]  = *(const float4*)(Ab + (size_t)(rA + 32 * i) * K + c4);
#pragma unroll
    for (int i = 0; i < 2; i++) rb2[i] = *(const float4*)(Wb + (size_t)(rA + 32 * i) * K + c4);
#pragma unroll
    for (int i = 0; i < 4; i++) {
        float4 v = ra[i];
        v.x = tf32r(v.x); v.y = tf32r(v.y); v.z = tf32r(v.z); v.w = tf32r(v.w);
        *(float4*)(As + (rA + 32 * i) * ASTR + c4) = v;
    }
#pragma unroll
    for (int i = 0; i < 2; i++) {
        float4 v = rb2[i];
        v.x = tf32r(v.x); v.y = tf32r(v.y); v.z = tf32r(v.z); v.w = tf32r(v.w);
        *(float4*)(Bs + (rA + 32 * i) * ASTR + c4) = v;
    }
    __syncthreads();

    for (int kt = 0; kt < nk; ++kt) {
        const int  cur  = kt & 1;
        const bool more = (kt + 1 < nk);
        if (more) {
            const int k0 = (kt + 1) * BK;
#pragma unroll
            for (int i = 0; i < 4; i++) ra[i]  = *(const float4*)(Ab + (size_t)(rA + 32 * i) * K + k0 + c4);
#pragma unroll
            for (int i = 0; i < 2; i++) rb2[i] = *(const float4*)(Wb + (size_t)(rA + 32 * i) * K + k0 + c4);
        }
        const float* Ac = As + cur * BM * ASTR;
        const float* Bc = Bs + cur * BN * ASTR;
#pragma unroll
        for (int kk = 0; kk < 4; kk++) {
            const int kb = kk * 8 + (lane & 3);
            uint32_t af[2][4];
#pragma unroll
            for (int mi = 0; mi < 2; mi++) {
                const int rb_ = wm * 32 + mi * 16 + (lane >> 2);
                af[mi][0] = __float_as_uint(Ac[rb_ * ASTR + kb]);
                af[mi][1] = __float_as_uint(Ac[(rb_ + 8) * ASTR + kb]);
                af[mi][2] = __float_as_uint(Ac[rb_ * ASTR + kb + 4]);
                af[mi][3] = __float_as_uint(Ac[(rb_ + 8) * ASTR + kb + 4]);
            }
            uint32_t bf[4][2];
#pragma unroll
            for (int ni = 0; ni < 4; ni++) {
                const int cb = wn * 32 + ni * 8 + (lane >> 2);
                bf[ni][0] = __float_as_uint(Bc[cb * ASTR + kb]);
                bf[ni][1] = __float_as_uint(Bc[cb * ASTR + kb + 4]);
            }
#pragma unroll
            for (int mi = 0; mi < 2; mi++)
#pragma unroll
                for (int ni = 0; ni < 4; ni++)
                    mma_tf32(acc[mi][ni], af[mi][0], af[mi][1], af[mi][2], af[mi][3],
                             bf[ni][0], bf[ni][1]);
        }
        if (more) {
            const int nxt = cur ^ 1;
#pragma unroll
            for (int i = 0; i < 4; i++) {
                float4 v = ra[i];
                v.x = tf32r(v.x); v.y = tf32r(v.y); v.z = tf32r(v.z); v.w = tf32r(v.w);
                *(float4*)(As + nxt * BM * ASTR + (rA + 32 * i) * ASTR + c4) = v;
            }
#pragma unroll
            for (int i = 0; i < 2; i++) {
                float4 v = rb2[i];
                v.x = tf32r(v.x); v.y = tf32r(v.y); v.z = tf32r(v.z); v.w = tf32r(v.w);
                *(float4*)(Bs + nxt * BN * ASTR + (rA + 32 * i) * ASTR + c4) = v;
            }
        }
        __syncthreads();
    }

    // write accum (+bias) to Cs
#pragma unroll
    for (int mi = 0; mi < 2; mi++) {
#pragma unroll
        for (int ni = 0; ni < 4; ni++) {
            const int r = wm * 32 + mi * 16 + (lane >> 2);
            const int c = wn * 32 + ni * 8 + 2 * (lane & 3);
            float b0 = 0.f, b1 = 0.f;
            if constexpr (EPI != EPI_LSTM) { b0 = bias[n0 + c]; b1 = bias[n0 + c + 1]; }
            Cs[r * CSTR + c]           = acc[mi][ni].x + b0;
            Cs[r * CSTR + c + 1]       = acc[mi][ni].y + b1;
            Cs[(r + 8) * CSTR + c]     = acc[mi][ni].z + b0;
            Cs[(r + 8) * CSTR + c + 1] = acc[mi][ni].w + b1;
        }
    }
    __syncthreads();

    // -------- fused epilogues --------
    if constexpr (EPI == EPI_GRU) {
        // Cs cols: unit-interleaved gates [r, z, i_n, h_n]; 16 units per block.
        for (int it = tid; it < BM * 16; it += NTH) {
            const int u = it & 15, row = it >> 4;
            const int jg = (n0 >> 2) + u;
            const float* cr = Cs + row * CSTR + 4 * u;
            const float rg = sigf(cr[0]);
            const float zg = sigf(cr[1]);
            const float nn = tanhf(cr[2] + rg * cr[3]);
            const float hp = A[(size_t)row * K + jg];      // h == previous x (K == HH)
            const float xn = (1.f - zg) * nn + zg * hp;
            out1[row * HH + jg] = xn;                      // next x
            out2[row * HH + jg] = fmaxf(xn, 0.f);          // relu into seq
        }
    } else if constexpr (EPI == EPI_LSTM) {
        for (int it = tid; it < BM * 16; it += NTH) {
            const int u = it & 15, row = it >> 4;
            const int jg = (n0 >> 2) + u;
            const float* cr = Cs + row * CSTR + 4 * u;
            const size_t xi = ((size_t)t * BB + row) * 4096 + n0 + 4 * u;
            const float ig = sigf(cr[0] + g_Xg[xi]);
            const float fg = sigf(cr[1] + g_Xg[xi + 1]);
            const float gg = tanhf(cr[2] + g_Xg[xi + 2]);
            const float og = sigf(cr[3] + g_Xg[xi + 3]);
            const int ci = row * LL + jg;
            const float cn = fg * g_c[ci] + ig * gg;
            g_c[ci] = cn;
            const float hn = og * tanhf(cn);
            out1[ci] = hn;                                  // next h
            g_hs[((size_t)t * BB + row) * LL + jg] = hn;    // [T,B,L]
        }
    } else if constexpr (EPI == EPI_XG) {
        for (int it = tid; it < BM * BN; it += NTH) {
            const int c = it & (BN - 1), row = it >> 6;
            g_Xg[(size_t)(m0 + row) * 4096 + n0 + c] = Cs[row * CSTR + c];
        }
    } else {  // EPI_FC
        for (int it = tid; it < BM * BN; it += NTH) {
            const int c = it & (BN - 1), row = it >> 6;
            const int m = m0 + row, tt = m >> 7, b = m & (BB - 1);
            out1[((size_t)b * TSTEPS + tt) * VV + n0 + c] = Cs[row * CSTR + c];
        }
    }
}

// ---------------- prep kernels ----------------
__global__ void prep_gru(const float* __restrict__ Wih, const float* __restrict__ Whh,
                         const float* __restrict__ bih, const float* __restrict__ bhh) {
    const int idx = blockIdx.x * blockDim.x + threadIdx.x;
    if (idx < 2048 * 512) {
        const int row = idx >> 9, k = idx & 511;
        const int j = row >> 2, g = row & 3;
        float wg, w1;
        if (g == 0)      { wg = Wih[j * 512 + k] + Whh[j * 512 + k];                 w1 = Whh[j * 512 + k]; }
        else if (g == 1) { wg = Wih[(512 + j) * 512 + k] + Whh[(512 + j) * 512 + k]; w1 = Whh[(512 + j) * 512 + k]; }
        else if (g == 2) { wg = Wih[(1024 + j) * 512 + k];                           w1 = 0.f; }
        else             { wg = Whh[(1024 + j) * 512 + k];                           w1 = wg; }
        g_Wg[idx] = wg; g_Wh1[idx] = w1;
    }
    if (idx < 2048) {
        const int j = idx >> 2, g = idx & 3;
        float b;
        if (g == 0)      b = bih[j] + bhh[j];
        else if (g == 1) b = bih[512 + j] + bhh[512 + j];
        else if (g == 2) b = bih[1024 + j];
        else             b = bhh[1024 + j];
        g_bg[idx] = b;
    }
}

__global__ void prep_lstm(const float* __restrict__ Wih, const float* __restrict__ Whh,
                          const float* __restrict__ bih, const float* __restrict__ bhh) {
    const int idx = blockIdx.x * blockDim.x + threadIdx.x;
    if (idx < 4096 * 1024) {
        const int row = idx >> 10, k = idx & 1023;
        const int j = row >> 2, p = row & 3;
        g_Whhl[idx] = Whh[(size_t)(p * 1024 + j) * 1024 + k];
    }
    if (idx < 4096 * 512) {
        const int row = idx >> 9, k = idx & 511;
        const int j = row >> 2, p = row & 3;
        g_Wihl[idx] = Wih[(size_t)(p * 1024 + j) * 512 + k];
    }
    if (idx < 4096) {
        const int j = idx >> 2, p = idx & 3;
        g_bl[idx] = bih[p * 1024 + j] + bhh[p * 1024 + j];
    }
}

__global__ void prep_zero() {
    const int idx = blockIdx.x * blockDim.x + threadIdx.x;
    if (idx < BB * LL) { g_h[idx] = 0.f; g_c[idx] = 0.f; }
    if (idx < BB * HH) g_seq[idx] = 0.f;   // seq[0] = relu(x0) = 0
}

// ---------------- host launcher ----------------
extern "C" void kernel_launch(void* const* d_in, const int* in_sizes, int n_in,
                              void* d_out, int out_size) {
    const float* z    = (const float*)d_in[0];
    const float* gWih = (const float*)d_in[2];
    const float* gWhh = (const float*)d_in[3];
    const float* gbih = (const float*)d_in[4];
    const float* gbhh = (const float*)d_in[5];
    const float* lWih = (const float*)d_in[6];
    const float* lWhh = (const float*)d_in[7];
    const float* lbih = (const float*)d_in[8];
    const float* lbhh = (const float*)d_in[9];
    const float* fcW  = (const float*)d_in[10];
    const float* fcb  = (const float*)d_in[11];
    float* out = (float*)d_out;

    cudaFuncSetAttribute(gemm_kernel<EPI_GRU>,  cudaFuncAttributeMaxDynamicSharedMemorySize, SMEM_BYTES);
    cudaFuncSetAttribute(gemm_kernel<EPI_LSTM>, cudaFuncAttributeMaxDynamicSharedMemorySize, SMEM_BYTES);
    cudaFuncSetAttribute(gemm_kernel<EPI_XG>,   cudaFuncAttributeMaxDynamicSharedMemorySize, SMEM_BYTES);
    cudaFuncSetAttribute(gemm_kernel<EPI_FC>,   cudaFuncAttributeMaxDynamicSharedMemorySize, SMEM_BYTES);

    float *pWg, *pWh1, *pbg, *pWihl, *pbl, *pWhhl, *px, *pseq, *ph, *phs;
    cudaGetSymbolAddress((void**)&pWg,   g_Wg);
    cudaGetSymbolAddress((void**)&pWh1,  g_Wh1);
    cudaGetSymbolAddress((void**)&pbg,   g_bg);
    cudaGetSymbolAddress((void**)&pWihl, g_Wihl);
    cudaGetSymbolAddress((void**)&pbl,   g_bl);
    cudaGetSymbolAddress((void**)&pWhhl, g_Whhl);
    cudaGetSymbolAddress((void**)&px,    g_x);
    cudaGetSymbolAddress((void**)&pseq,  g_seq);
    cudaGetSymbolAddress((void**)&ph,    g_h);
    cudaGetSymbolAddress((void**)&phs,   g_hs);

    prep_gru <<<(2048 * 512 + 255) / 256, 256>>>(gWih, gWhh, gbih, gbhh);
    prep_lstm<<<(4096 * 1024 + 255) / 256, 256>>>(lWih, lWhh, lbih, lbhh);
    prep_zero<<<(BB * LL + 255) / 256, 256>>>();

    // ---- autoregressive GRU: 255 sequential steps ----
    // t = 1: x = 0, h = z  (special weight matrix with zeroed i_n rows)
    gemm_kernel<EPI_GRU><<<2048 / BN, NTH, SMEM_BYTES>>>(
        z, pWh1, pbg, HH, 0, px + BB * HH, pseq + (size_t)BB * HH);
    // t >= 2: x == h == x_{t-1}, combined weights
    for (int t = 2; t < TSTEPS; ++t) {
        const float* a = px + (size_t)((t - 1) & 1) * BB * HH;
        float* xo      = px + (size_t)(t & 1) * BB * HH;
        gemm_kernel<EPI_GRU><<<2048 / BN, NTH, SMEM_BYTES>>>(
            a, pWg, pbg, HH, 0, xo, pseq + (size_t)t * BB * HH);
    }

    // ---- LSTM input-side gates for all timesteps (parallel GEMM) ----
    {
        dim3 grid(4096 / BN, (TSTEPS * BB) / BM);   // 64 x 256
        gemm_kernel<EPI_XG><<<grid, NTH, SMEM_BYTES>>>(
            pseq, pWihl, pbl, HH, 0, nullptr, nullptr);
    }

    // ---- LSTM recurrence: 256 sequential steps ----
    for (int t = 0; t < TSTEPS; ++t) {
        gemm_kernel<EPI_LSTM><<<4096 / BN, NTH, SMEM_BYTES>>>(
            ph + (size_t)(t & 1) * BB * LL, pWhhl, nullptr, LL, t,
            ph + (size_t)((t + 1) & 1) * BB * LL, nullptr);
    }

    // ---- FC: logits = hs @ fcW^T + fcb, permuted to [B,T,V] ----
    {
        dim3 grid(VV / BN, (TSTEPS * BB) / BM);     // 16 x 256
        gemm_kernel<EPI_FC><<<grid, NTH, SMEM_BYTES>>>(
            phs, fcW, fcb, LL, 0, out, nullptr);
    }
}

// round 2
// speedup vs baseline: 1.3789x; 1.3789x over previous
#include <cuda_runtime.h>
#include <cstdint>
#include <cstddef>

// ---------------- problem constants ----------------
#define TSTEPS 256
#define BB 128      // batch
#define HH 512      // GRU hidden
#define LL 1024     // LSTM hidden
#define VV 1024     // vocab

// ---------------- GEMM tile config (generic kernel) ----------------
#define BM 128
#define BN 64
#define BK 32
#define NTH 256
#define APAD 4
#define ASTR (BK + APAD)            // 36 floats per smem row
#define SMEM_BYTES ((2*BM*ASTR + 2*BN*ASTR) * 4)   // 55296
#define CSTR (BN + 4)

// persistent-kernel smem weight strides (stride mod 32 == 4 -> conflict-free)
#define WSTR_G (HH + 4)             // 516
#define WSTR_L (LL + 4)             // 1028
#define SMEM_GRU_P ((64 * WSTR_G + 2*BM*ASTR) * 4)   // 168960
#define SMEM_LSTM_P ((32 * WSTR_L + 2*BM*ASTR) * 4)  // 168448

// ---------------- persistent device scratch ----------------
__device__ __align__(256) float g_Wg  [2048 * 512];   // GRU combined weights (t>=2), unit-interleaved [r,z,in,hn]
__device__ __align__(256) float g_Wh1 [2048 * 512];   // GRU step-1 weights (x=0 path)
__device__ __align__(256) float g_bg  [2048];         // GRU combined bias
__device__ __align__(256) float g_Wihl[4096 * 512];   // LSTM Wih, unit-interleaved [i,f,g,o]
__device__ __align__(256) float g_bl  [4096];         // LSTM bih+bhh, interleaved
__device__ __align__(256) float g_Whhl[4096 * 1024];  // LSTM Whh, unit-interleaved
__device__ __align__(256) float g_x   [2 * BB * HH];  // GRU state ping-pong
__device__ __align__(256) float g_seq [TSTEPS * BB * HH];          // relu(x_t)
__device__ __align__(256) float g_Xg  [(size_t)TSTEPS * BB * 4096];// LSTM input gates (+bias)
__device__ __align__(256) float g_h   [2 * BB * LL];  // LSTM h ping-pong
__device__ __align__(256) float g_c   [BB * LL];      // LSTM c
__device__ __align__(256) float g_hs  [(size_t)TSTEPS * BB * LL];  // LSTM outputs [T,B,L]
__device__ unsigned g_bar_gru;
__device__ unsigned g_bar_lstm;

// ---------------- helpers ----------------
__device__ __forceinline__ float tf32r(float x) {
    uint32_t u;
    asm("cvt.rna.tf32.f32 %0, %1;" : "=r"(u) : "f"(x));
    return __uint_as_float(u);
}

__device__ __forceinline__ void mma_tf32(float4& d,
                                         uint32_t a0, uint32_t a1, uint32_t a2, uint32_t a3,
                                         uint32_t b0, uint32_t b1) {
    asm volatile(
        "mma.sync.aligned.m16n8k8.row.col.f32.tf32.tf32.f32 "
        "{%0,%1,%2,%3}, {%4,%5,%6,%7}, {%8,%9}, {%0,%1,%2,%3};\n"
        : "+f"(d.x), "+f"(d.y), "+f"(d.z), "+f"(d.w)
        : "r"(a0), "r"(a1), "r"(a2), "r"(a3), "r"(b0), "r"(b1));
}

__device__ __forceinline__ float sigf(float x) { return 1.0f / (1.0f + expf(-x)); }

__device__ __forceinline__ void grid_bar(unsigned* bar, unsigned target) {
    __syncthreads();
    if (threadIdx.x == 0) {
        __threadfence();
        atomicAdd(bar, 1u);
        unsigned v;
        do {
            asm volatile("ld.acquire.gpu.b32 %0, [%1];" : "=r"(v) : "l"(bar));
        } while (v < target);
    }
    __syncthreads();
}

enum { EPI_GRU = 0, EPI_XG = 2, EPI_FC = 3 };

// ---------------- unified tiled GEMM (C[BMxBN] = A[BM,K] * W[BN,K]^T) ----------------
template <int EPI>
__global__ void __launch_bounds__(NTH)
gemm_kernel(const float* __restrict__ A, const float* __restrict__ W,
            const float* __restrict__ bias, int K,
            float* __restrict__ out1, float* __restrict__ out2) {
    extern __shared__ float sm[];
    float* As = sm;                      // [2][BM][ASTR]
    float* Bs = sm + 2 * BM * ASTR;      // [2][BN][ASTR]
    float* Cs = sm;                      // [BM][CSTR]

    const int tid  = threadIdx.x;
    const int lane = tid & 31;
    const int wid  = tid >> 5;
    const int wm   = wid & 3;
    const int wn   = wid >> 2;
    const int n0   = blockIdx.x * BN;
    const int m0   = (EPI == EPI_XG || EPI == EPI_FC) ? (int)blockIdx.y * BM : 0;

    const float* Ab = A + (size_t)m0 * K;
    const float* Wb = W + (size_t)n0 * K;
    const int rA = tid >> 3;
    const int c4 = (tid & 7) * 4;

    float4 acc[2][4];
#pragma unroll
    for (int mi = 0; mi < 2; mi++)
#pragma unroll
        for (int ni = 0; ni < 4; ni++) acc[mi][ni] = make_float4(0.f, 0.f, 0.f, 0.f);

    float4 ra[4], rb2[2];
    const int nk = K >> 5;

#pragma unroll
    for (int i = 0; i < 4; i++) ra[i]  = *(const float4*)(Ab + (size_t)(rA + 32 * i) * K + c4);
#pragma unroll
    for (int i = 0; i < 2; i++) rb2[i] = *(const float4*)(Wb + (size_t)(rA + 32 * i) * K + c4);
#pragma unroll
    for (int i = 0; i < 4; i++) {
        float4 v = ra[i];
        v.x = tf32r(v.x); v.y = tf32r(v.y); v.z = tf32r(v.z); v.w = tf32r(v.w);
        *(float4*)(As + (rA + 32 * i) * ASTR + c4) = v;
    }
#pragma unroll
    for (int i = 0; i < 2; i++) {
        float4 v = rb2[i];
        v.x = tf32r(v.x); v.y = tf32r(v.y); v.z = tf32r(v.z); v.w = tf32r(v.w);
        *(float4*)(Bs + (rA + 32 * i) * ASTR + c4) = v;
    }
    __syncthreads();

    for (int kt = 0; kt < nk; ++kt) {
        const int  cur  = kt & 1;
        const bool more = (kt + 1 < nk);
        if (more) {
            const int k0 = (kt + 1) * BK;
#pragma unroll
            for (int i = 0; i < 4; i++) ra[i]  = *(const float4*)(Ab + (size_t)(rA + 32 * i) * K + k0 + c4);
#pragma unroll
            for (int i = 0; i < 2; i++) rb2[i] = *(const float4*)(Wb + (size_t)(rA + 32 * i) * K + k0 + c4);
        }
        const float* Ac = As + cur * BM * ASTR;
        const float* Bc = Bs + cur * BN * ASTR;
#pragma unroll
        for (int kk = 0; kk < 4; kk++) {
            const int kb = kk * 8 + (lane & 3);
            uint32_t af[2][4];
#pragma unroll
            for (int mi = 0; mi < 2; mi++) {
                const int rb_ = wm * 32 + mi * 16 + (lane >> 2);
                af[mi][0] = __float_as_uint(Ac[rb_ * ASTR + kb]);
                af[mi][1] = __float_as_uint(Ac[(rb_ + 8) * ASTR + kb]);
                af[mi][2] = __float_as_uint(Ac[rb_ * ASTR + kb + 4]);
                af[mi][3] = __float_as_uint(Ac[(rb_ + 8) * ASTR + kb + 4]);
            }
            uint32_t bf[4][2];
#pragma unroll
            for (int ni = 0; ni < 4; ni++) {
                const int cb = wn * 32 + ni * 8 + (lane >> 2);
                bf[ni][0] = __float_as_uint(Bc[cb * ASTR + kb]);
                bf[ni][1] = __float_as_uint(Bc[cb * ASTR + kb + 4]);
            }
#pragma unroll
            for (int mi = 0; mi < 2; mi++)
#pragma unroll
                for (int ni = 0; ni < 4; ni++)
                    mma_tf32(acc[mi][ni], af[mi][0], af[mi][1], af[mi][2], af[mi][3],
                             bf[ni][0], bf[ni][1]);
        }
        if (more) {
            const int nxt = cur ^ 1;
#pragma unroll
            for (int i = 0; i < 4; i++) {
                float4 v = ra[i];
                v.x = tf32r(v.x); v.y = tf32r(v.y); v.z = tf32r(v.z); v.w = tf32r(v.w);
                *(float4*)(As + nxt * BM * ASTR + (rA + 32 * i) * ASTR + c4) = v;
            }
#pragma unroll
            for (int i = 0; i < 2; i++) {
                float4 v = rb2[i];
                v.x = tf32r(v.x); v.y = tf32r(v.y); v.z = tf32r(v.z); v.w = tf32r(v.w);
                *(float4*)(Bs + nxt * BN * ASTR + (rA + 32 * i) * ASTR + c4) = v;
            }
        }
        __syncthreads();
    }

#pragma unroll
    for (int mi = 0; mi < 2; mi++) {
#pragma unroll
        for (int ni = 0; ni < 4; ni++) {
            const int r = wm * 32 + mi * 16 + (lane >> 2);
            const int c = wn * 32 + ni * 8 + 2 * (lane & 3);
            const float b0 = bias[n0 + c], b1 = bias[n0 + c + 1];
            Cs[r * CSTR + c]           = acc[mi][ni].x + b0;
            Cs[r * CSTR + c + 1]       = acc[mi][ni].y + b1;
            Cs[(r + 8) * CSTR + c]     = acc[mi][ni].z + b0;
            Cs[(r + 8) * CSTR + c + 1] = acc[mi][ni].w + b1;
        }
    }
    __syncthreads();

    if constexpr (EPI == EPI_GRU) {
        for (int it = tid; it < BM * 16; it += NTH) {
            const int u = it & 15, row = it >> 4;
            const int jg = (n0 >> 2) + u;
            const float* cr = Cs + row * CSTR + 4 * u;
            const float rg = sigf(cr[0]);
            const float zg = sigf(cr[1]);
            const float nn = tanhf(cr[2] + rg * cr[3]);
            const float hp = A[(size_t)row * K + jg];
            const float xn = (1.f - zg) * nn + zg * hp;
            out1[row * HH + jg] = xn;
            out2[row * HH + jg] = fmaxf(xn, 0.f);
        }
    } else if constexpr (EPI == EPI_XG) {
        for (int it = tid; it < BM * BN; it += NTH) {
            const int c = it & (BN - 1), row = it >> 6;
            g_Xg[(size_t)(m0 + row) * 4096 + n0 + c] = Cs[row * CSTR + c];
        }
    } else {  // EPI_FC
        for (int it = tid; it < BM * BN; it += NTH) {
            const int c = it & (BN - 1), row = it >> 6;
            const int m = m0 + row, tt = m >> 7, b = m & (BB - 1);
            out1[((size_t)b * TSTEPS + tt) * VV + n0 + c] = Cs[row * CSTR + c];
        }
    }
}

// ---------------- persistent GRU recurrence: steps t = 2..255, grid = 32 ----------------
__global__ void __launch_bounds__(NTH)
gru_persist() {
    extern __shared__ float sm[];
    float* Ws = sm;                          // [64][WSTR_G]
    float* As = sm + 64 * WSTR_G;            // [2][BM][ASTR]
    float* Cs = As;                          // reused after mainloop of each step

    const int tid  = threadIdx.x;
    const int lane = tid & 31;
    const int wid  = tid >> 5;
    const int wm   = wid & 3;
    const int wn   = wid >> 2;
    const int n0   = blockIdx.x * 64;

    // load weight tile once (tf32-rounded)
    for (int i = tid; i < 64 * (HH / 4); i += NTH) {
        const int r = i >> 7, c = (i & 127) << 2;
        float4 v = *(const float4*)(g_Wg + (size_t)(n0 + r) * HH + c);
        v.x = tf32r(v.x); v.y = tf32r(v.y); v.z = tf32r(v.z); v.w = tf32r(v.w);
        *(float4*)(Ws + r * WSTR_G + c) = v;
    }

    const int rA = tid >> 3;
    const int c4 = (tid & 7) * 4;

    for (int t = 2; t < TSTEPS; ++t) {
        const float* Ab = g_x + (size_t)((t - 1) & 1) * BB * HH;
        float* xo       = g_x + (size_t)(t & 1) * BB * HH;
        float* so       = g_seq + (size_t)t * BB * HH;

        float4 acc[2][4];
#pragma unroll
        for (int mi = 0; mi < 2; mi++)
#pragma unroll
            for (int ni = 0; ni < 4; ni++) acc[mi][ni] = make_float4(0.f, 0.f, 0.f, 0.f);

        float4 ra[4];
#pragma unroll
        for (int i = 0; i < 4; i++) ra[i] = *(const float4*)(Ab + (size_t)(rA + 32 * i) * HH + c4);
#pragma unroll
        for (int i = 0; i < 4; i++) {
            float4 v = ra[i];
            v.x = tf32r(v.x); v.y = tf32r(v.y); v.z = tf32r(v.z); v.w = tf32r(v.w);
            *(float4*)(As + (rA + 32 * i) * ASTR + c4) = v;
        }
        __syncthreads();

        for (int kt = 0; kt < (HH / BK); ++kt) {
            const int  cur  = kt & 1;
            const bool more = (kt + 1 < (HH / BK));
            if (more) {
                const int k0 = (kt + 1) * BK;
#pragma unroll
                for (int i = 0; i < 4; i++)
                    ra[i] = *(const float4*)(Ab + (size_t)(rA + 32 * i) * HH + k0 + c4);
            }
            const float* Ac = As + cur * BM * ASTR;
#pragma unroll
            for (int kk = 0; kk < 4; kk++) {
                const int kb = kk * 8 + (lane & 3);
                const int kg = kt * BK + kb;
                uint32_t af[2][4];
#pragma unroll
                for (int mi = 0; mi < 2; mi++) {
                    const int rb_ = wm * 32 + mi * 16 + (lane >> 2);
                    af[mi][0] = __float_as_uint(Ac[rb_ * ASTR + kb]);
                    af[mi][1] = __float_as_uint(Ac[(rb_ + 8) * ASTR + kb]);
                    af[mi][2] = __float_as_uint(Ac[rb_ * ASTR + kb + 4]);
                    af[mi][3] = __float_as_uint(Ac[(rb_ + 8) * ASTR + kb + 4]);
                }
                uint32_t bf[4][2];
#pragma unroll
                for (int ni = 0; ni < 4; ni++) {
                    const int cb = wn * 32 + ni * 8 + (lane >> 2);
                    bf[ni][0] = __float_as_uint(Ws[cb * WSTR_G + kg]);
                    bf[ni][1] = __float_as_uint(Ws[cb * WSTR_G + kg + 4]);
                }
#pragma unroll
                for (int mi = 0; mi < 2; mi++)
#pragma unroll
                    for (int ni = 0; ni < 4; ni++)
                        mma_tf32(acc[mi][ni], af[mi][0], af[mi][1], af[mi][2], af[mi][3],
                                 bf[ni][0], bf[ni][1]);
            }
            if (more) {
                const int nxt = cur ^ 1;
#pragma unroll
                for (int i = 0; i < 4; i++) {
                    float4 v = ra[i];
                    v.x = tf32r(v.x); v.y = tf32r(v.y); v.z = tf32r(v.z); v.w = tf32r(v.w);
                    *(float4*)(As + nxt * BM * ASTR + (rA + 32 * i) * ASTR + c4) = v;
                }
            }
            __syncthreads();
        }

#pragma unroll
        for (int mi = 0; mi < 2; mi++) {
#pragma unroll
            for (int ni = 0; ni < 4; ni++) {
                const int r = wm * 32 + mi * 16 + (lane >> 2);
                const int c = wn * 32 + ni * 8 + 2 * (lane & 3);
                Cs[r * CSTR + c]           = acc[mi][ni].x + g_bg[n0 + c];
                Cs[r * CSTR + c + 1]       = acc[mi][ni].y + g_bg[n0 + c + 1];
                Cs[(r + 8) * CSTR + c]     = acc[mi][ni].z + g_bg[n0 + c];
                Cs[(r + 8) * CSTR + c + 1] = acc[mi][ni].w + g_bg[n0 + c + 1];
            }
        }
        __syncthreads();

        for (int it = tid; it < BM * 16; it += NTH) {
            const int u = it & 15, row = it >> 4;
            const int jg = (n0 >> 2) + u;
            const float* cr = Cs + row * CSTR + 4 * u;
            const float rg = sigf(cr[0]);
            const float zg = sigf(cr[1]);
            const float nn = tanhf(cr[2] + rg * cr[3]);
            const float hp = Ab[(size_t)row * HH + jg];
            const float xn = (1.f - zg) * nn + zg * hp;
            xo[row * HH + jg] = xn;
            so[row * HH + jg] = fmaxf(xn, 0.f);
        }

        grid_bar(&g_bar_gru, 32u * (unsigned)(t - 1));
    }
}

// ---------------- persistent LSTM recurrence: steps t = 0..255, grid = 128 ----------------
__global__ void __launch_bounds__(NTH)
lstm_persist() {
    extern __shared__ float sm[];
    float* Ws = sm;                          // [32][WSTR_L]
    float* As = sm + 32 * WSTR_L;            // [2][BM][ASTR]
    float* Cs = As;

    const int tid  = threadIdx.x;
    const int lane = tid & 31;
    const int wid  = tid >> 5;
    const int wm   = wid & 3;
    const int wn   = wid >> 2;                // 0..1, 16 cols each
    const int n0   = blockIdx.x * 32;

    // load weight tile once (tf32-rounded)
    for (int i = tid; i < 32 * (LL / 4); i += NTH) {
        const int r = i >> 8, c = (i & 255) << 2;
        float4 v = *(const float4*)(g_Whhl + (size_t)(n0 + r) * LL + c);
        v.x = tf32r(v.x); v.y = tf32r(v.y); v.z = tf32r(v.z); v.w = tf32r(v.w);
        *(float4*)(Ws + r * WSTR_L + c) = v;
    }

    const int rA = tid >> 3;
    const int c4 = (tid & 7) * 4;

    for (int t = 0; t < TSTEPS; ++t) {
        const float* Ab = g_h + (size_t)(t & 1) * BB * LL;
        float* ho       = g_h + (size_t)((t + 1) & 1) * BB * LL;

        float4 acc[2][2];
#pragma unroll
        for (int mi = 0; mi < 2; mi++)
#pragma unroll
            for (int ni = 0; ni < 2; ni++) acc[mi][ni] = make_float4(0.f, 0.f, 0.f, 0.f);

        float4 ra[4];
#pragma unroll
        for (int i = 0; i < 4; i++) ra[i] = *(const float4*)(Ab + (size_t)(rA + 32 * i) * LL + c4);
#pragma unroll
        for (int i = 0; i < 4; i++) {
            float4 v = ra[i];
            v.x = tf32r(v.x); v.y = tf32r(v.y); v.z = tf32r(v.z); v.w = tf32r(v.w);
            *(float4*)(As + (rA + 32 * i) * ASTR + c4) = v;
        }
        __syncthreads();

        for (int kt = 0; kt < (LL / BK); ++kt) {
            const int  cur  = kt & 1;
            const bool more = (kt + 1 < (LL / BK));
            if (more) {
                const int k0 = (kt + 1) * BK;
#pragma unroll
                for (int i = 0; i < 4; i++)
                    ra[i] = *(const float4*)(Ab + (size_t)(rA + 32 * i) * LL + k0 + c4);
            }
            const float* Ac = As + cur * BM * ASTR;
#pragma unroll
            for (int kk = 0; kk < 4; kk++) {
                const int kb = kk * 8 + (lane & 3);
                const int kg = kt * BK + kb;
                uint32_t af[2][4];
#pragma unroll
                for (int mi = 0; mi < 2; mi++) {
                    const int rb_ = wm * 32 + mi * 16 + (lane >> 2);
                    af[mi][0] = __float_as_uint(Ac[rb_ * ASTR + kb]);
                    af[mi][1] = __float_as_uint(Ac[(rb_ + 8) * ASTR + kb]);
                    af[mi][2] = __float_as_uint(Ac[rb_ * ASTR + kb + 4]);
                    af[mi][3] = __float_as_uint(Ac[(rb_ + 8) * ASTR + kb + 4]);
                }
                uint32_t bf[2][2];
#pragma unroll
                for (int ni = 0; ni < 2; ni++) {
                    const int cb = wn * 16 + ni * 8 + (lane >> 2);
                    bf[ni][0] = __float_as_uint(Ws[cb * WSTR_L + kg]);
                    bf[ni][1] = __float_as_uint(Ws[cb * WSTR_L + kg + 4]);
                }
#pragma unroll
                for (int mi = 0; mi < 2; mi++)
#pragma unroll
                    for (int ni = 0; ni < 2; ni++)
                        mma_tf32(acc[mi][ni], af[mi][0], af[mi][1], af[mi][2], af[mi][3],
                                 bf[ni][0], bf[ni][1]);
            }
            if (more) {
                const int nxt = cur ^ 1;
#pragma unroll
                for (int i = 0; i < 4; i++) {
                    float4 v = ra[i];
                    v.x = tf32r(v.x); v.y = tf32r(v.y); v.z = tf32r(v.z); v.w = tf32r(v.w);
                    *(float4*)(As + nxt * BM * ASTR + (rA + 32 * i) * ASTR + c4) = v;
                }
            }
            __syncthreads();
        }

#pragma unroll
        for (int mi = 0; mi < 2; mi++) {
#pragma unroll
            for (int ni = 0; ni < 2; ni++) {
                const int r = wm * 32 + mi * 16 + (lane >> 2);
                const int c = wn * 16 + ni * 8 + 2 * (lane & 3);
                Cs[r * CSTR + c]           = acc[mi][ni].x;
                Cs[r * CSTR + c + 1]       = acc[mi][ni].y;
                Cs[(r + 8) * CSTR + c]     = acc[mi][ni].z;
                Cs[(r + 8) * CSTR + c + 1] = acc[mi][ni].w;
            }
        }
        __syncthreads();

        for (int it = tid; it < BM * 8; it += NTH) {
            const int u = it & 7, row = it >> 3;
            const int jg = (n0 >> 2) + u;
            const float* cr = Cs + row * CSTR + 4 * u;
            const size_t xi = ((size_t)t * BB + row) * 4096 + n0 + 4 * u;
            const float ig = sigf(cr[0] + g_Xg[xi]);
            const float fg = sigf(cr[1] + g_Xg[xi + 1]);
            const float gg = tanhf(cr[2] + g_Xg[xi + 2]);
            const float og = sigf(cr[3] + g_Xg[xi + 3]);
            const int ci = row * LL + jg;
            const float cn = fg * g_c[ci] + ig * gg;
            g_c[ci] = cn;
            const float hn = og * tanhf(cn);
            ho[ci] = hn;
            g_hs[((size_t)t * BB + row) * LL + jg] = hn;
        }

        grid_bar(&g_bar_lstm, 128u * (unsigned)(t + 1));
    }
}

// ---------------- prep kernels ----------------
__global__ void prep_gru(const float* __restrict__ Wih, const float* __restrict__ Whh,
                         const float* __restrict__ bih, const float* __restrict__ bhh) {
    const int idx = blockIdx.x * blockDim.x + threadIdx.x;
    if (idx < 2048 * 512) {
        const int row = idx >> 9, k = idx & 511;
        const int j = row >> 2, g = row & 3;
        float wg, w1;
        if (g == 0)      { wg = Wih[j * 512 + k] + Whh[j * 512 + k];                 w1 = Whh[j * 512 + k]; }
        else if (g == 1) { wg = Wih[(512 + j) * 512 + k] + Whh[(512 + j) * 512 + k]; w1 = Whh[(512 + j) * 512 + k]; }
        else if (g == 2) { wg = Wih[(1024 + j) * 512 + k];                           w1 = 0.f; }
        else             { wg = Whh[(1024 + j) * 512 + k];                           w1 = wg; }
        g_Wg[idx] = wg; g_Wh1[idx] = w1;
    }
    if (idx < 2048) {
        const int j = idx >> 2, g = idx & 3;
        float b;
        if (g == 0)      b = bih[j] + bhh[j];
        else if (g == 1) b = bih[512 + j] + bhh[512 + j];
        else if (g == 2) b = bih[1024 + j];
        else             b = bhh[1024 + j];
        g_bg[idx] = b;
    }
}

__global__ void prep_lstm(const float* __restrict__ Wih, const float* __restrict__ Whh,
                          const float* __restrict__ bih, const float* __restrict__ bhh) {
    const int idx = blockIdx.x * blockDim.x + threadIdx.x;
    if (idx < 4096 * 1024) {
        const int row = idx >> 10, k = idx & 1023;
        const int j = row >> 2, p = row & 3;
        g_Whhl[idx] = Whh[(size_t)(p * 1024 + j) * 1024 + k];
    }
    if (idx < 4096 * 512) {
        const int row = idx >> 9, k = idx & 511;
        const int j = row >> 2, p = row & 3;
        g_Wihl[idx] = Wih[(size_t)(p * 1024 + j) * 512 + k];
    }
    if (idx < 4096) {
        const int j = idx >> 2, p = idx & 3;
        g_bl[idx] = bih[p * 1024 + j] + bhh[p * 1024 + j];
    }
}

__global__ void prep_zero() {
    const int idx = blockIdx.x * blockDim.x + threadIdx.x;
    if (idx < BB * LL) { g_h[idx] = 0.f; g_c[idx] = 0.f; }
    if (idx < BB * HH) g_seq[idx] = 0.f;
    if (idx == 0) { g_bar_gru = 0u; g_bar_lstm = 0u; }
}

// ---------------- host launcher ----------------
extern "C" void kernel_launch(void* const* d_in, const int* in_sizes, int n_in,
                              void* d_out, int out_size) {
    const float* z    = (const float*)d_in[0];
    const float* gWih = (const float*)d_in[2];
    const float* gWhh = (const float*)d_in[3];
    const float* gbih = (const float*)d_in[4];
    const float* gbhh = (const float*)d_in[5];
    const float* lWih = (const float*)d_in[6];
    const float* lWhh = (const float*)d_in[7];
    const float* lbih = (const float*)d_in[8];
    const float* lbhh = (const float*)d_in[9];
    const float* fcW  = (const float*)d_in[10];
    const float* fcb  = (const float*)d_in[11];
    float* out = (float*)d_out;

    cudaFuncSetAttribute(gemm_kernel<EPI_GRU>, cudaFuncAttributeMaxDynamicSharedMemorySize, SMEM_BYTES);
    cudaFuncSetAttribute(gemm_kernel<EPI_XG>,  cudaFuncAttributeMaxDynamicSharedMemorySize, SMEM_BYTES);
    cudaFuncSetAttribute(gemm_kernel<EPI_FC>,  cudaFuncAttributeMaxDynamicSharedMemorySize, SMEM_BYTES);
    cudaFuncSetAttribute(gru_persist,  cudaFuncAttributeMaxDynamicSharedMemorySize, SMEM_GRU_P);
    cudaFuncSetAttribute(lstm_persist, cudaFuncAttributeMaxDynamicSharedMemorySize, SMEM_LSTM_P);

    float *pWh1, *pbg, *pWihl, *pbl, *px, *pseq, *phs;
    cudaGetSymbolAddress((void**)&pWh1,  g_Wh1);
    cudaGetSymbolAddress((void**)&pbg,   g_bg);
    cudaGetSymbolAddress((void**)&pWihl, g_Wihl);
    cudaGetSymbolAddress((void**)&pbl,   g_bl);
    cudaGetSymbolAddress((void**)&px,    g_x);
    cudaGetSymbolAddress((void**)&pseq,  g_seq);
    cudaGetSymbolAddress((void**)&phs,   g_hs);

    prep_gru <<<(2048 * 512 + 255) / 256, 256>>>(gWih, gWhh, gbih, gbhh);
    prep_lstm<<<(4096 * 1024 + 255) / 256, 256>>>(lWih, lWhh, lbih, lbhh);
    prep_zero<<<(BB * LL + 255) / 256, 256>>>();

    // ---- GRU step 1 (x=0, h=z): one classic launch ----
    gemm_kernel<EPI_GRU><<<2048 / BN, NTH, SMEM_BYTES>>>(
        z, pWh1, pbg, HH, px + BB * HH, pseq + (size_t)BB * HH);

    // ---- GRU steps 2..255: persistent kernel, weights SMEM-resident ----
    gru_persist<<<32, NTH, SMEM_GRU_P>>>();

    // ---- LSTM input-side gates for all timesteps (parallel GEMM) ----
    {
        dim3 grid(4096 / BN, (TSTEPS * BB) / BM);   // 64 x 256
        gemm_kernel<EPI_XG><<<grid, NTH, SMEM_BYTES>>>(
            pseq, pWihl, pbl, HH, nullptr, nullptr);
    }

    // ---- LSTM recurrence: persistent kernel, weights SMEM-resident ----
    lstm_persist<<<128, NTH, SMEM_LSTM_P>>>();

    // ---- FC: logits = hs @ fcW^T + fcb, permuted to [B,T,V] ----
    {
        dim3 grid(VV / BN, (TSTEPS * BB) / BM);     // 16 x 256
        gemm_kernel<EPI_FC><<<grid, NTH, SMEM_BYTES>>>(
            phs, fcW, fcb, LL, out, nullptr);
    }
}

// round 3
// speedup vs baseline: 2.5193x; 1.8270x over previous
#include <cuda_runtime.h>
#include <cuda_fp16.h>
#include <cstdint>
#include <cstddef>

// ---------------- problem constants ----------------
#define TSTEPS 256
#define BB 128      // batch
#define HH 512      // GRU hidden
#define LL 1024     // LSTM hidden
#define VV 1024     // vocab

// ---------------- tf32 GEMM tile config (XG / FC) ----------------
#define BM 128
#define BN 64
#define BK 32
#define NTH 256
#define APAD 4
#define ASTR (BK + APAD)
#define SMEM_BYTES ((2*BM*ASTR + 2*BN*ASTR) * 4)   // 55296
#define CSTR (BN + 4)

// ---------------- fp16 persistent-kernel config ----------------
#define PBN 32                      // cols per CTA (8 gate-interleaved units)
#define PBK 64                      // k per tile (4 x k16)
#define ASTRH (PBK + 8)             // 72 halfs
#define WSTRH_G (HH + 8)            // 520 halfs
#define WSTRH_L (LL + 8)            // 1032 halfs
#define PCSTR 36                    // fp32 Cs stride
#define SMEM_GRU_P  ((32*WSTRH_G + 2*BM*ASTRH) * 2)   // 33280+36864 = 70144
#define SMEM_LSTM_P ((32*WSTRH_L + 2*BM*ASTRH) * 2)   // 66048+36864 = 102912

// ---------------- persistent device scratch ----------------
__device__ __align__(256) __half g_Wgh [2048 * 512];   // GRU combined weights (t>=2), fp16, gate-interleaved
__device__ __align__(256) __half g_Wg1h[2048 * 512];   // GRU step-1 weights (x=0 path), fp16
__device__ __align__(256) float  g_bg  [2048];         // GRU combined bias
__device__ __align__(256) float  g_Wihl[4096 * 512];   // LSTM Wih fp32 (XG gemm), gate-interleaved
__device__ __align__(256) float  g_bl  [4096];         // LSTM bih+bhh, interleaved
__device__ __align__(256) __half g_Whhlh[4096 * 1024]; // LSTM Whh fp16, gate-interleaved
__device__ __align__(256) float  g_x   [2 * BB * HH];  // GRU state fp32 ping-pong
__device__ __align__(256) __half g_xh  [2 * BB * HH];  // GRU state fp16 (matmul operand)
__device__ __align__(256) __half g_zh  [BB * HH];      // half(z)
__device__ __align__(256) float  g_seq [TSTEPS * BB * HH];          // relu(x_t) fp32 (XG input)
__device__ __align__(256) float  g_Xg  [(size_t)TSTEPS * BB * 4096];// LSTM input gates (+bias)
__device__ __align__(256) __half g_hh  [2 * BB * LL];  // LSTM h fp16 ping-pong (matmul operand)
__device__ __align__(256) float  g_c   [BB * LL];      // LSTM c fp32
__device__ __align__(256) float  g_hs  [(size_t)TSTEPS * BB * LL];  // LSTM outputs [T,B,L] fp32
__device__ unsigned g_bar_gru;
__device__ unsigned g_bar_lstm;

// ---------------- helpers ----------------
__device__ __forceinline__ float tf32r(float x) {
    uint32_t u;
    asm("cvt.rna.tf32.f32 %0, %1;" : "=r"(u) : "f"(x));
    return __uint_as_float(u);
}

__device__ __forceinline__ void mma_tf32(float4& d,
                                         uint32_t a0, uint32_t a1, uint32_t a2, uint32_t a3,
                                         uint32_t b0, uint32_t b1) {
    asm volatile(
        "mma.sync.aligned.m16n8k8.row.col.f32.tf32.tf32.f32 "
        "{%0,%1,%2,%3}, {%4,%5,%6,%7}, {%8,%9}, {%0,%1,%2,%3};\n"
        : "+f"(d.x), "+f"(d.y), "+f"(d.z), "+f"(d.w)
        : "r"(a0), "r"(a1), "r"(a2), "r"(a3), "r"(b0), "r"(b1));
}

__device__ __forceinline__ void mma_f16(float4& d,
                                        uint32_t a0, uint32_t a1, uint32_t a2, uint32_t a3,
                                        uint32_t b0, uint32_t b1) {
    asm volatile(
        "mma.sync.aligned.m16n8k16.row.col.f32.f16.f16.f32 "
        "{%0,%1,%2,%3}, {%4,%5,%6,%7}, {%8,%9}, {%0,%1,%2,%3};\n"
        : "+f"(d.x), "+f"(d.y), "+f"(d.z), "+f"(d.w)
        : "r"(a0), "r"(a1), "r"(a2), "r"(a3), "r"(b0), "r"(b1));
}

__device__ __forceinline__ float sigf(float x) { return 1.0f / (1.0f + expf(-x)); }

__device__ __forceinline__ void grid_bar(unsigned* bar, unsigned target) {
    __syncthreads();
    if (threadIdx.x == 0) {
        __threadfence();
        atomicAdd(bar, 1u);
        unsigned v;
        do {
            asm volatile("ld.acquire.gpu.b32 %0, [%1];" : "=r"(v) : "l"(bar));
        } while (v < target);
    }
    __syncthreads();
}

enum { EPI_XG = 2, EPI_FC = 3 };

// ---------------- tf32 tiled GEMM (C[BMxBN] = A[BM,K] * W[BN,K]^T), XG/FC ----------------
template <int EPI>
__global__ void __launch_bounds__(NTH)
gemm_kernel(const float* __restrict__ A, const float* __restrict__ W,
            const float* __restrict__ bias, int K,
            float* __restrict__ out1) {
    extern __shared__ float sm[];
    float* As = sm;
    float* Bs = sm + 2 * BM * ASTR;
    float* Cs = sm;

    const int tid  = threadIdx.x;
    const int lane = tid & 31;
    const int wid  = tid >> 5;
    const int wm   = wid & 3;
    const int wn   = wid >> 2;
    const int n0   = blockIdx.x * BN;
    const int m0   = (int)blockIdx.y * BM;

    const float* Ab = A + (size_t)m0 * K;
    const float* Wb = W + (size_t)n0 * K;
    const int rA = tid >> 3;
    const int c4 = (tid & 7) * 4;

    float4 acc[2][4];
#pragma unroll
    for (int mi = 0; mi < 2; mi++)
#pragma unroll
        for (int ni = 0; ni < 4; ni++) acc[mi][ni] = make_float4(0.f, 0.f, 0.f, 0.f);

    float4 ra[4], rb2[2];
    const int nk = K >> 5;

#pragma unroll
    for (int i = 0; i < 4; i++) ra[i]  = *(const float4*)(Ab + (size_t)(rA + 32 * i) * K + c4);
#pragma unroll
    for (int i = 0; i < 2; i++) rb2[i] = *(const float4*)(Wb + (size_t)(rA + 32 * i) * K + c4);
#pragma unroll
    for (int i = 0; i < 4; i++) {
        float4 v = ra[i];
        v.x = tf32r(v.x); v.y = tf32r(v.y); v.z = tf32r(v.z); v.w = tf32r(v.w);
        *(float4*)(As + (rA + 32 * i) * ASTR + c4) = v;
    }
#pragma unroll
    for (int i = 0; i < 2; i++) {
        float4 v = rb2[i];
        v.x = tf32r(v.x); v.y = tf32r(v.y); v.z = tf32r(v.z); v.w = tf32r(v.w);
        *(float4*)(Bs + (rA + 32 * i) * ASTR + c4) = v;
    }
    __syncthreads();

    for (int kt = 0; kt < nk; ++kt) {
        const int  cur  = kt & 1;
        const bool more = (kt + 1 < nk);
        if (more) {
            const int k0 = (kt + 1) * BK;
#pragma unroll
            for (int i = 0; i < 4; i++) ra[i]  = *(const float4*)(Ab + (size_t)(rA + 32 * i) * K + k0 + c4);
#pragma unroll
            for (int i = 0; i < 2; i++) rb2[i] = *(const float4*)(Wb + (size_t)(rA + 32 * i) * K + k0 + c4);
        }
        const float* Ac = As + cur * BM * ASTR;
        const float* Bc = Bs + cur * BN * ASTR;
#pragma unroll
        for (int kk = 0; kk < 4; kk++) {
            const int kb = kk * 8 + (lane & 3);
            uint32_t af[2][4];
#pragma unroll
            for (int mi = 0; mi < 2; mi++) {
                const int rb_ = wm * 32 + mi * 16 + (lane >> 2);
                af[mi][0] = __float_as_uint(Ac[rb_ * ASTR + kb]);
                af[mi][1] = __float_as_uint(Ac[(rb_ + 8) * ASTR + kb]);
                af[mi][2] = __float_as_uint(Ac[rb_ * ASTR + kb + 4]);
                af[mi][3] = __float_as_uint(Ac[(rb_ + 8) * ASTR + kb + 4]);
            }
            uint32_t bf[4][2];
#pragma unroll
            for (int ni = 0; ni < 4; ni++) {
                const int cb = wn * 32 + ni * 8 + (lane >> 2);
                bf[ni][0] = __float_as_uint(Bc[cb * ASTR + kb]);
                bf[ni][1] = __float_as_uint(Bc[cb * ASTR + kb + 4]);
            }
#pragma unroll
            for (int mi = 0; mi < 2; mi++)
#pragma unroll
                for (int ni = 0; ni < 4; ni++)
                    mma_tf32(acc[mi][ni], af[mi][0], af[mi][1], af[mi][2], af[mi][3],
                             bf[ni][0], bf[ni][1]);
        }
        if (more) {
            const int nxt = cur ^ 1;
#pragma unroll
            for (int i = 0; i < 4; i++) {
                float4 v = ra[i];
                v.x = tf32r(v.x); v.y = tf32r(v.y); v.z = tf32r(v.z); v.w = tf32r(v.w);
                *(float4*)(As + nxt * BM * ASTR + (rA + 32 * i) * ASTR + c4) = v;
            }
#pragma unroll
            for (int i = 0; i < 2; i++) {
                float4 v = rb2[i];
                v.x = tf32r(v.x); v.y = tf32r(v.y); v.z = tf32r(v.z); v.w = tf32r(v.w);
                *(float4*)(Bs + nxt * BN * ASTR + (rA + 32 * i) * ASTR + c4) = v;
            }
        }
        __syncthreads();
    }

#pragma unroll
    for (int mi = 0; mi < 2; mi++) {
#pragma unroll
        for (int ni = 0; ni < 4; ni++) {
            const int r = wm * 32 + mi * 16 + (lane >> 2);
            const int c = wn * 32 + ni * 8 + 2 * (lane & 3);
            const float b0 = bias[n0 + c], b1 = bias[n0 + c + 1];
            Cs[r * CSTR + c]           = acc[mi][ni].x + b0;
            Cs[r * CSTR + c + 1]       = acc[mi][ni].y + b1;
            Cs[(r + 8) * CSTR + c]     = acc[mi][ni].z + b0;
            Cs[(r + 8) * CSTR + c + 1] = acc[mi][ni].w + b1;
        }
    }
    __syncthreads();

    if constexpr (EPI == EPI_XG) {
        for (int it = tid; it < BM * BN; it += NTH) {
            const int c = it & (BN - 1), row = it >> 6;
            g_Xg[(size_t)(m0 + row) * 4096 + n0 + c] = Cs[row * CSTR + c];
        }
    } else {  // EPI_FC
        for (int it = tid; it < BM * BN; it += NTH) {
            const int c = it & (BN - 1), row = it >> 6;
            const int m = m0 + row, tt = m >> 7, b = m & (BB - 1);
            out1[((size_t)b * TSTEPS + tt) * VV + n0 + c] = Cs[row * CSTR + c];
        }
    }
}

// ---------------- persistent GRU recurrence: steps t = 1..255, grid = 64, fp16 mma ----------------
__global__ void __launch_bounds__(NTH)
gru_persist(const float* __restrict__ z) {
    extern __shared__ __half smh[];
    __half* Ws = smh;                         // [32][WSTRH_G]
    __half* As = smh + 32 * WSTRH_G;          // [2][128][ASTRH]
    float*  Cs = (float*)As;                  // reuse after mainloop

    const int tid  = threadIdx.x;
    const int lane = tid & 31;
    const int wid  = tid >> 5;
    const int wm   = wid & 3;    // 32 rows each
    const int wn   = wid >> 2;   // 16 cols each
    const int n0   = blockIdx.x * PBN;

    // load step-1 weights (fp16, unit-interleaved)
    {
        const __half* src = g_Wg1h + (size_t)n0 * HH;
        for (int i = tid; i < 32 * (HH / 8); i += NTH) {
            const int r = i / (HH / 8), c = (i % (HH / 8)) * 8;
            *(uint4*)(Ws + r * WSTRH_G + c) = *(const uint4*)(src + (size_t)r * HH + c);
        }
    }
    __syncthreads();

    const int rL  = tid >> 3;          // 0..31
    const int ch  = (tid & 7) * 8;     // half-col chunk

    for (int t = 1; t < TSTEPS; ++t) {
        const __half* Abh = (t == 1) ? g_zh : g_xh + (size_t)((t - 1) & 1) * BB * HH;
        const float*  hp32 = (t == 1) ? z   : g_x  + (size_t)((t - 1) & 1) * BB * HH;
        float*  xo32 = g_x  + (size_t)(t & 1) * BB * HH;
        __half* xoh  = g_xh + (size_t)(t & 1) * BB * HH;
        float*  so   = g_seq + (size_t)t * BB * HH;

        // prefetch h_prev for epilogue
        float hp[4];
#pragma unroll
        for (int r = 0; r < 4; r++)
            hp[r] = hp32[(size_t)((tid >> 3) + 32 * r) * HH + (n0 >> 2) + (tid & 7)];

        float4 acc[2][2];
#pragma unroll
        for (int mi = 0; mi < 2; mi++)
#pragma unroll
            for (int ni = 0; ni < 2; ni++) acc[mi][ni] = make_float4(0.f, 0.f, 0.f, 0.f);

        uint4 pr[4];
#pragma unroll
        for (int i = 0; i < 4; i++)
            pr[i] = *(const uint4*)(Abh + (size_t)(rL + 32 * i) * HH + ch);
#pragma unroll
        for (int i = 0; i < 4; i++)
            *(uint4*)(As + (rL + 32 * i) * ASTRH + ch) = pr[i];
        __syncthreads();

        const int NK = HH / PBK;   // 8
        for (int kt = 0; kt < NK; ++kt) {
            const int  cur  = kt & 1;
            const bool more = (kt + 1 < NK);
            if (more) {
                const int k0 = (kt + 1) * PBK;
#pragma unroll
                for (int i = 0; i < 4; i++)
                    pr[i] = *(const uint4*)(Abh + (size_t)(rL + 32 * i) * HH + k0 + ch);
            }
            const __half* Ac = As + cur * BM * ASTRH;
#pragma unroll
            for (int kk = 0; kk < 4; kk++) {
                const int kb = kk * 16 + 2 * (lane & 3);
                const int kg = kt * PBK + kb;
                uint32_t af[2][4];
#pragma unroll
                for (int mi = 0; mi < 2; mi++) {
                    const __half* ap = Ac + (wm * 32 + mi * 16 + (lane >> 2)) * ASTRH + kb;
                    af[mi][0] = *(const uint32_t*)(ap);
                    af[mi][1] = *(const uint32_t*)(ap + 8 * ASTRH);
                    af[mi][2] = *(const uint32_t*)(ap + 8);
                    af[mi][3] = *(const uint32_t*)(ap + 8 * ASTRH + 8);
                }
                uint32_t bf[2][2];
#pragma unroll
                for (int ni = 0; ni < 2; ni++) {
                    const __half* wp = Ws + (wn * 16 + ni * 8 + (lane >> 2)) * WSTRH_G + kg;
                    bf[ni][0] = *(const uint32_t*)(wp);
                    bf[ni][1] = *(const uint32_t*)(wp + 8);
                }
#pragma unroll
                for (int mi = 0; mi < 2; mi++)
#pragma unroll
                    for (int ni = 0; ni < 2; ni++)
                        mma_f16(acc[mi][ni], af[mi][0], af[mi][1], af[mi][2], af[mi][3],
                                bf[ni][0], bf[ni][1]);
            }
            if (more) {
                const int nxt = cur ^ 1;
#pragma unroll
                for (int i = 0; i < 4; i++)
                    *(uint4*)(As + nxt * BM * ASTRH + (rL + 32 * i) * ASTRH + ch) = pr[i];
            }
            __syncthreads();
        }

        // accum (+bias) -> Cs
#pragma unroll
        for (int mi = 0; mi < 2; mi++) {
#pragma unroll
            for (int ni = 0; ni < 2; ni++) {
                const int r = wm * 32 + mi * 16 + (lane >> 2);
                const int c = wn * 16 + ni * 8 + 2 * (lane & 3);
                const float b0 = g_bg[n0 + c], b1 = g_bg[n0 + c + 1];
                Cs[r * PCSTR + c]           = acc[mi][ni].x + b0;
                Cs[r * PCSTR + c + 1]       = acc[mi][ni].y + b1;
                Cs[(r + 8) * PCSTR + c]     = acc[mi][ni].z + b0;
                Cs[(r + 8) * PCSTR + c + 1] = acc[mi][ni].w + b1;
            }
        }
        __syncthreads();

        // GRU cell epilogue (8 units per CTA)
#pragma unroll
        for (int r = 0; r < 4; r++) {
            const int row = (tid >> 3) + 32 * r;
            const int u   = tid & 7;
            const int jg  = (n0 >> 2) + u;
            const float4 cv = *(const float4*)(Cs + row * PCSTR + 4 * u);
            const float rg = sigf(cv.x);
            const float zg = sigf(cv.y);
            const float nn = tanhf(cv.z + rg * cv.w);
            const float xn = (1.f - zg) * nn + zg * hp[r];
            const int oi = row * HH + jg;
            xo32[oi] = xn;
            xoh[oi]  = __float2half_rn(xn);
            so[oi]   = fmaxf(xn, 0.f);
        }

        if (t < TSTEPS - 1) {
            grid_bar(&g_bar_gru, 64u * (unsigned)t);
            if (t == 1) {
                const __half* src = g_Wgh + (size_t)n0 * HH;
                for (int i = tid; i < 32 * (HH / 8); i += NTH) {
                    const int r = i / (HH / 8), c = (i % (HH / 8)) * 8;
                    *(uint4*)(Ws + r * WSTRH_G + c) = *(const uint4*)(src + (size_t)r * HH + c);
                }
                __syncthreads();
            }
        }
    }
}

// ---------------- persistent LSTM recurrence: steps t = 0..255, grid = 128, fp16 mma ----------------
__global__ void __launch_bounds__(NTH)
lstm_persist() {
    extern __shared__ __half smh[];
    __half* Ws = smh;                         // [32][WSTRH_L]
    __half* As = smh + 32 * WSTRH_L;          // [2][128][ASTRH]
    float*  Cs = (float*)As;

    const int tid  = threadIdx.x;
    const int lane = tid & 31;
    const int wid  = tid >> 5;
    const int wm   = wid & 3;
    const int wn   = wid >> 2;
    const int n0   = blockIdx.x * PBN;

    {
        const __half* src = g_Whhlh + (size_t)n0 * LL;
        for (int i = tid; i < 32 * (LL / 8); i += NTH) {
            const int r = i / (LL / 8), c = (i % (LL / 8)) * 8;
            *(uint4*)(Ws + r * WSTRH_L + c) = *(const uint4*)(src + (size_t)r * LL + c);
        }
    }
    __syncthreads();

    const int rL = tid >> 3;
    const int ch = (tid & 7) * 8;

    for (int t = 0; t < TSTEPS; ++t) {
        const __half* Abh = g_hh + (size_t)(t & 1) * BB * LL;
        __half* hoh       = g_hh + (size_t)((t + 1) & 1) * BB * LL;

        // prefetch Xg (float4 per item) and c
        float4 xg[4];
        float  cc[4];
#pragma unroll
        for (int r = 0; r < 4; r++) {
            const int row = (tid >> 3) + 32 * r;
            const int u   = tid & 7;
            xg[r] = *(const float4*)(g_Xg + ((size_t)t * BB + row) * 4096 + n0 + 4 * u);
            cc[r] = g_c[row * LL + (n0 >> 2) + u];
        }

        float4 acc[2][2];
#pragma unroll
        for (int mi = 0; mi < 2; mi++)
#pragma unroll
            for (int ni = 0; ni < 2; ni++) acc[mi][ni] = make_float4(0.f, 0.f, 0.f, 0.f);

        uint4 pr[4];
#pragma unroll
        for (int i = 0; i < 4; i++)
            pr[i] = *(const uint4*)(Abh + (size_t)(rL + 32 * i) * LL + ch);
#pragma unroll
        for (int i = 0; i < 4; i++)
            *(uint4*)(As + (rL + 32 * i) * ASTRH + ch) = pr[i];
        __syncthreads();

        const int NK = LL / PBK;   // 16
        for (int kt = 0; kt < NK; ++kt) {
            const int  cur  = kt & 1;
            const bool more = (kt + 1 < NK);
            if (more) {
                const int k0 = (kt + 1) * PBK;
#pragma unroll
                for (int i = 0; i < 4; i++)
                    pr[i] = *(const uint4*)(Abh + (size_t)(rL + 32 * i) * LL + k0 + ch);
            }
            const __half* Ac = As + cur * BM * ASTRH;
#pragma unroll
            for (int kk = 0; kk < 4; kk++) {
                const int kb = kk * 16 + 2 * (lane & 3);
                const int kg = kt * PBK + kb;
                uint32_t af[2][4];
#pragma unroll
                for (int mi = 0; mi < 2; mi++) {
                    const __half* ap = Ac + (wm * 32 + mi * 16 + (lane >> 2)) * ASTRH + kb;
                    af[mi][0] = *(const uint32_t*)(ap);
                    af[mi][1] = *(const uint32_t*)(ap + 8 * ASTRH);
                    af[mi][2] = *(const uint32_t*)(ap + 8);
                    af[mi][3] = *(const uint32_t*)(ap + 8 * ASTRH + 8);
                }
                uint32_t bf[2][2];
#pragma unroll
                for (int ni = 0; ni < 2; ni++) {
                    const __half* wp = Ws + (wn * 16 + ni * 8 + (lane >> 2)) * WSTRH_L + kg;
                    bf[ni][0] = *(const uint32_t*)(wp);
                    bf[ni][1] = *(const uint32_t*)(wp + 8);
                }
#pragma unroll
                for (int mi = 0; mi < 2; mi++)
#pragma unroll
                    for (int ni = 0; ni < 2; ni++)
                        mma_f16(acc[mi][ni], af[mi][0], af[mi][1], af[mi][2], af[mi][3],
                                bf[ni][0], bf[ni][1]);
            }
            if (more) {
                const int nxt = cur ^ 1;
#pragma unroll
                for (int i = 0; i < 4; i++)
                    *(uint4*)(As + nxt * BM * ASTRH + (rL + 32 * i) * ASTRH + ch) = pr[i];
            }
            __syncthreads();
        }

#pragma unroll
        for (int mi = 0; mi < 2; mi++) {
#pragma unroll
            for (int ni = 0; ni < 2; ni++) {
                const int r = wm * 32 + mi * 16 + (lane >> 2);
                const int c = wn * 16 + ni * 8 + 2 * (lane & 3);
                Cs[r * PCSTR + c]           = acc[mi][ni].x;
                Cs[r * PCSTR + c + 1]       = acc[mi][ni].y;
                Cs[(r + 8) * PCSTR + c]     = acc[mi][ni].z;
                Cs[(r + 8) * PCSTR + c + 1] = acc[mi][ni].w;
            }
        }
        __syncthreads();

        // LSTM cell epilogue (8 units per CTA)
#pragma unroll
        for (int r = 0; r < 4; r++) {
            const int row = (tid >> 3) + 32 * r;
            const int u   = tid & 7;
            const int jg  = (n0 >> 2) + u;
            const float4 cv = *(const float4*)(Cs + row * PCSTR + 4 * u);
            const float ig = sigf(cv.x + xg[r].x);
            const float fg = sigf(cv.y + xg[r].y);
            const float gg = tanhf(cv.z + xg[r].z);
            const float og = sigf(cv.w + xg[r].w);
            const int ci = row * LL + jg;
            const float cn = fg * cc[r] + ig * gg;
            g_c[ci] = cn;
            const float hn = og * tanhf(cn);
            hoh[ci] = __float2half_rn(hn);
            g_hs[((size_t)t * BB + row) * LL + jg] = hn;
        }

        if (t < TSTEPS - 1)
            grid_bar(&g_bar_lstm, 128u * (unsigned)(t + 1));
    }
}

// ---------------- prep kernels ----------------
__global__ void prep_gru(const float* __restrict__ Wih, const float* __restrict__ Whh,
                         const float* __restrict__ bih, const float* __restrict__ bhh) {
    const int idx = blockIdx.x * blockDim.x + threadIdx.x;
    if (idx < 2048 * 512) {
        const int row = idx >> 9, k = idx & 511;
        const int j = row >> 2, g = row & 3;
        float wg, w1;
        if (g == 0)      { wg = Wih[j * 512 + k] + Whh[j * 512 + k];                 w1 = Whh[j * 512 + k]; }
        else if (g == 1) { wg = Wih[(512 + j) * 512 + k] + Whh[(512 + j) * 512 + k]; w1 = Whh[(512 + j) * 512 + k]; }
        else if (g == 2) { wg = Wih[(1024 + j) * 512 + k];                           w1 = 0.f; }
        else             { wg = Whh[(1024 + j) * 512 + k];                           w1 = wg; }
        g_Wgh[idx]  = __float2half_rn(wg);
        g_Wg1h[idx] = __float2half_rn(w1);
    }
    if (idx < 2048) {
        const int j = idx >> 2, g = idx & 3;
        float b;
        if (g == 0)      b = bih[j] + bhh[j];
        else if (g == 1) b = bih[512 + j] + bhh[512 + j];
        else if (g == 2) b = bih[1024 + j];
        else             b = bhh[1024 + j];
        g_bg[idx] = b;
    }
}

__global__ void prep_lstm(const float* __restrict__ Wih, const float* __restrict__ Whh,
                          const float* __restrict__ bih, const float* __restrict__ bhh) {
    const int idx = blockIdx.x * blockDim.x + threadIdx.x;
    if (idx < 4096 * 1024) {
        const int row = idx >> 10, k = idx & 1023;
        const int j = row >> 2, p = row & 3;
        g_Whhlh[idx] = __float2half_rn(Whh[(size_t)(p * 1024 + j) * 1024 + k]);
    }
    if (idx < 4096 * 512) {
        const int row = idx >> 9, k = idx & 511;
        const int j = row >> 2, p = row & 3;
        g_Wihl[idx] = Wih[(size_t)(p * 1024 + j) * 512 + k];
    }
    if (idx < 4096) {
        const int j = idx >> 2, p = idx & 3;
        g_bl[idx] = bih[p * 1024 + j] + bhh[p * 1024 + j];
    }
}

__global__ void prep_zero(const float* __restrict__ z) {
    const int idx = blockIdx.x * blockDim.x + threadIdx.x;
    if (idx < BB * LL) { g_hh[idx] = __float2half_rn(0.f); g_c[idx] = 0.f; }
    if (idx < BB * HH) { g_zh[idx] = __float2half_rn(z[idx]); g_seq[idx] = 0.f; }
    if (idx == 0) { g_bar_gru = 0u; g_bar_lstm = 0u; }
}

// ---------------- host launcher ----------------
extern "C" void kernel_launch(void* const* d_in, const int* in_sizes, int n_in,
                              void* d_out, int out_size) {
    const float* z    = (const float*)d_in[0];
    const float* gWih = (const float*)d_in[2];
    const float* gWhh = (const float*)d_in[3];
    const float* gbih = (const float*)d_in[4];
    const float* gbhh = (const float*)d_in[5];
    const float* lWih = (const float*)d_in[6];
    const float* lWhh = (const float*)d_in[7];
    const float* lbih = (const float*)d_in[8];
    const float* lbhh = (const float*)d_in[9];
    const float* fcW  = (const float*)d_in[10];
    const float* fcb  = (const float*)d_in[11];
    float* out = (float*)d_out;

    cudaFuncSetAttribute(gemm_kernel<EPI_XG>, cudaFuncAttributeMaxDynamicSharedMemorySize, SMEM_BYTES);
    cudaFuncSetAttribute(gemm_kernel<EPI_FC>, cudaFuncAttributeMaxDynamicSharedMemorySize, SMEM_BYTES);
    cudaFuncSetAttribute(gru_persist,  cudaFuncAttributeMaxDynamicSharedMemorySize, SMEM_GRU_P);
    cudaFuncSetAttribute(lstm_persist, cudaFuncAttributeMaxDynamicSharedMemorySize, SMEM_LSTM_P);

    float *pWihl, *pbl, *pseq, *phs;
    cudaGetSymbolAddress((void**)&pWihl, g_Wihl);
    cudaGetSymbolAddress((void**)&pbl,   g_bl);
    cudaGetSymbolAddress((void**)&pseq,  g_seq);
    cudaGetSymbolAddress((void**)&phs,   g_hs);

    prep_gru <<<(2048 * 512 + 255) / 256, 256>>>(gWih, gWhh, gbih, gbhh);
    prep_lstm<<<(4096 * 1024 + 255) / 256, 256>>>(lWih, lWhh, lbih, lbhh);
    prep_zero<<<(BB * LL + 255) / 256, 256>>>(z);

    // ---- GRU chain: one persistent kernel, steps 1..255 (step 1 folded) ----
    gru_persist<<<64, NTH, SMEM_GRU_P>>>(z);

    // ---- LSTM input-side gates for all timesteps (parallel tf32 GEMM) ----
    {
        dim3 grid(4096 / BN, (TSTEPS * BB) / BM);   // 64 x 256
        gemm_kernel<EPI_XG><<<grid, NTH, SMEM_BYTES>>>(pseq, pWihl, pbl, HH, nullptr);
    }

    // ---- LSTM chain: one persistent kernel ----
    lstm_persist<<<128, NTH, SMEM_LSTM_P>>>();

    // ---- FC: logits = hs @ fcW^T + fcb, permuted to [B,T,V] ----
    {
        dim3 grid(VV / BN, (TSTEPS * BB) / BM);     // 16 x 256
        gemm_kernel<EPI_FC><<<grid, NTH, SMEM_BYTES>>>(phs, fcW, fcb, LL, out);
    }
}

// round 4
// speedup vs baseline: 3.3593x; 1.3334x over previous
#include <cuda_runtime.h>
#include <cuda_fp16.h>
#include <cstdint>
#include <cstddef>

// ---------------- problem constants ----------------
#define TSTEPS 256
#define BB 128      // batch
#define HH 512      // GRU hidden
#define LL 1024     // LSTM hidden
#define VV 1024     // vocab

// ---------------- fp16 kernel config ----------------
#define NTH 256
#define BM 128
#define PBN 32                      // chain cols per CTA
#define PBK 64                      // k per tile (4 x k16)
#define ASTRH (PBK + 8)             // 72 halfs
#define WSTRH_G (HH + 8)            // 520 halfs
#define WSTRH_L (LL + 8)            // 1032 halfs
#define PCSTR 36                    // fp32 Cs stride (chain epilogue staging)

#define SMEM_A_KERN ((64*WSTRH_G + 2*BM*ASTRH) * 2)   // 103424 (XG side dominates)
#define SMEM_B_KERN ((32*WSTRH_L + 2*BM*ASTRH) * 2)   // 102912

// ---------------- persistent device scratch ----------------
__device__ __align__(256) __half g_Wgh  [2048 * 512];   // GRU combined weights (t>=2), gate-interleaved
__device__ __align__(256) __half g_Wg1h [2048 * 512];   // GRU step-1 weights (x=0 path)
__device__ __align__(256) float  g_bg   [2048];         // GRU combined bias
__device__ __align__(256) __half g_Wihlh[4096 * 512];   // LSTM Wih fp16, gate-interleaved
__device__ __align__(256) float  g_bl   [4096];         // LSTM bih+bhh, interleaved
__device__ __align__(256) __half g_Whhlh[4096 * 1024];  // LSTM Whh fp16, gate-interleaved
__device__ __align__(256) __half g_fcWh [1024 * 1024];  // fc weights fp16
__device__ __align__(256) float  g_x    [2 * BB * HH];  // GRU state fp32 ping-pong
__device__ __align__(256) __half g_xh   [2 * BB * HH];  // GRU state fp16 (matmul operand)
__device__ __align__(256) __half g_zh   [BB * HH];      // half(z)
__device__ __align__(256) __half g_seqh [TSTEPS * BB * HH];          // relu(x_t) fp16
__device__ __align__(256) float  g_Xg   [(size_t)TSTEPS * BB * 4096];// LSTM input gates (+bias) fp32
__device__ __align__(256) __half g_hh   [2 * BB * LL];  // LSTM h fp16 ping-pong
__device__ __align__(256) float  g_c    [BB * LL];      // LSTM c fp32
__device__ __align__(256) __half g_hsh  [(size_t)TSTEPS * BB * LL];  // LSTM outputs [T,B,L] fp16
__device__ unsigned g_bar_gru;
__device__ unsigned g_bar_lstm;
__device__ unsigned g_fc_cnt;

// ---------------- helpers ----------------
__device__ __forceinline__ void mma_f16(float4& d,
                                        uint32_t a0, uint32_t a1, uint32_t a2, uint32_t a3,
                                        uint32_t b0, uint32_t b1) {
    asm volatile(
        "mma.sync.aligned.m16n8k16.row.col.f32.f16.f16.f32 "
        "{%0,%1,%2,%3}, {%4,%5,%6,%7}, {%8,%9}, {%0,%1,%2,%3};\n"
        : "+f"(d.x), "+f"(d.y), "+f"(d.z), "+f"(d.w)
        : "r"(a0), "r"(a1), "r"(a2), "r"(a3), "r"(b0), "r"(b1));
}

__device__ __forceinline__ float sigf(float x) { return 1.0f / (1.0f + expf(-x)); }

// arrive: all CTA writes done -> fence -> count
__device__ __forceinline__ void bar_arrive(unsigned* bar) {
    __syncthreads();
    if (threadIdx.x == 0) { __threadfence(); atomicAdd(bar, 1u); }
}
// wait until count >= target (thread0 acquire-poll + CTA barrier)
__device__ __forceinline__ void wait_ge(unsigned* bar, unsigned target) {
    if (threadIdx.x == 0) {
        unsigned v;
        do {
            asm volatile("ld.acquire.gpu.b32 %0, [%1];" : "=r"(v) : "l"(bar));
        } while (v < target);
    }
    __syncthreads();
}

// ============================================================================
// Kernel A: grid 128.  CTAs 0-63: GRU chain (PBN=32 cols each).
//                      CTAs 64-127: XG = seq_t @ Wih^T + bl, overlapped per-step.
// ============================================================================
__global__ void __launch_bounds__(NTH)
gruxg_persist(const float* __restrict__ z) {
    extern __shared__ __half smh[];
    const int tid  = threadIdx.x;
    const int lane = tid & 31;
    const int wid  = tid >> 5;
    const int wm   = wid & 3;
    const int wn   = wid >> 2;
    const int rL   = tid >> 3;         // 0..31
    const int ch   = (tid & 7) * 8;    // half-chunk col

    if (blockIdx.x < 64) {
        // ---------------- GRU chain ----------------
        __half* Ws = smh;                         // [32][WSTRH_G]
        __half* As = smh + 32 * WSTRH_G;          // [2][128][ASTRH]
        float*  Cs = (float*)As;
        const int n0 = blockIdx.x * PBN;

        // step-1 weights
        for (int i = tid; i < 32 * 64; i += NTH) {
            const int r = i >> 6, c = (i & 63) * 8;
            *(uint4*)(Ws + r * WSTRH_G + c) = *(const uint4*)(g_Wg1h + (size_t)(n0 + r) * HH + c);
        }
        __syncthreads();

        for (int t = 1; t < TSTEPS; ++t) {
            const __half* Abh  = (t == 1) ? g_zh : g_xh + (size_t)((t - 1) & 1) * BB * HH;
            const float*  hp32 = (t == 1) ? z    : g_x  + (size_t)((t - 1) & 1) * BB * HH;
            float*  xo32 = g_x   + (size_t)(t & 1) * BB * HH;
            __half* xoh  = g_xh  + (size_t)(t & 1) * BB * HH;
            __half* so   = g_seqh + (size_t)t * BB * HH;

            float hp[4];
#pragma unroll
            for (int r = 0; r < 4; r++)
                hp[r] = hp32[(size_t)(rL + 32 * r) * HH + (n0 >> 2) + (tid & 7)];

            float4 acc[2][2];
#pragma unroll
            for (int mi = 0; mi < 2; mi++)
#pragma unroll
                for (int ni = 0; ni < 2; ni++) acc[mi][ni] = make_float4(0.f, 0.f, 0.f, 0.f);

            uint4 pr[4];
#pragma unroll
            for (int i = 0; i < 4; i++)
                pr[i] = *(const uint4*)(Abh + (size_t)(rL + 32 * i) * HH + ch);
#pragma unroll
            for (int i = 0; i < 4; i++)
                *(uint4*)(As + (rL + 32 * i) * ASTRH + ch) = pr[i];
            __syncthreads();

            const int NK = HH / PBK;   // 8
            for (int kt = 0; kt < NK; ++kt) {
                const int  cur  = kt & 1;
                const bool more = (kt + 1 < NK);
                if (more) {
                    const int k0 = (kt + 1) * PBK;
#pragma unroll
                    for (int i = 0; i < 4; i++)
                        pr[i] = *(const uint4*)(Abh + (size_t)(rL + 32 * i) * HH + k0 + ch);
                }
                const __half* Ac = As + cur * BM * ASTRH;
#pragma unroll
                for (int kk = 0; kk < 4; kk++) {
                    const int kb = kk * 16 + 2 * (lane & 3);
                    const int kg = kt * PBK + kb;
                    uint32_t af[2][4];
#pragma unroll
                    for (int mi = 0; mi < 2; mi++) {
                        const __half* ap = Ac + (wm * 32 + mi * 16 + (lane >> 2)) * ASTRH + kb;
                        af[mi][0] = *(const uint32_t*)(ap);
                        af[mi][1] = *(const uint32_t*)(ap + 8 * ASTRH);
                        af[mi][2] = *(const uint32_t*)(ap + 8);
                        af[mi][3] = *(const uint32_t*)(ap + 8 * ASTRH + 8);
                    }
                    uint32_t bf[2][2];
#pragma unroll
                    for (int ni = 0; ni < 2; ni++) {
                        const __half* wp = Ws + (wn * 16 + ni * 8 + (lane >> 2)) * WSTRH_G + kg;
                        bf[ni][0] = *(const uint32_t*)(wp);
                        bf[ni][1] = *(const uint32_t*)(wp + 8);
                    }
#pragma unroll
                    for (int mi = 0; mi < 2; mi++)
#pragma unroll
                        for (int ni = 0; ni < 2; ni++)
                            mma_f16(acc[mi][ni], af[mi][0], af[mi][1], af[mi][2], af[mi][3],
                                    bf[ni][0], bf[ni][1]);
                }
                if (more) {
                    const int nxt = cur ^ 1;
#pragma unroll
                    for (int i = 0; i < 4; i++)
                        *(uint4*)(As + nxt * BM * ASTRH + (rL + 32 * i) * ASTRH + ch) = pr[i];
                }
                __syncthreads();
            }

#pragma unroll
            for (int mi = 0; mi < 2; mi++) {
#pragma unroll
                for (int ni = 0; ni < 2; ni++) {
                    const int r = wm * 32 + mi * 16 + (lane >> 2);
                    const int c = wn * 16 + ni * 8 + 2 * (lane & 3);
                    const float b0 = g_bg[n0 + c], b1 = g_bg[n0 + c + 1];
                    Cs[r * PCSTR + c]           = acc[mi][ni].x + b0;
                    Cs[r * PCSTR + c + 1]       = acc[mi][ni].y + b1;
                    Cs[(r + 8) * PCSTR + c]     = acc[mi][ni].z + b0;
                    Cs[(r + 8) * PCSTR + c + 1] = acc[mi][ni].w + b1;
                }
            }
            __syncthreads();

#pragma unroll
            for (int r = 0; r < 4; r++) {
                const int row = rL + 32 * r;
                const int u   = tid & 7;
                const int jg  = (n0 >> 2) + u;
                const float4 cv = *(const float4*)(Cs + row * PCSTR + 4 * u);
                const float rg = sigf(cv.x);
                const float zg = sigf(cv.y);
                const float nn = tanhf(cv.z + rg * cv.w);
                const float xn = (1.f - zg) * nn + zg * hp[r];
                const int oi = row * HH + jg;
                xo32[oi] = xn;
                xoh[oi]  = __float2half_rn(xn);
                so[oi]   = __float2half_rn(fmaxf(xn, 0.f));
            }

            bar_arrive(&g_bar_gru);
            if (t < TSTEPS - 1) {
                wait_ge(&g_bar_gru, 64u * (unsigned)t);
                if (t == 1) {
                    for (int i = tid; i < 32 * 64; i += NTH) {
                        const int r = i >> 6, c = (i & 63) * 8;
                        *(uint4*)(Ws + r * WSTRH_G + c) =
                            *(const uint4*)(g_Wgh + (size_t)(n0 + r) * HH + c);
                    }
                    __syncthreads();
                }
            }
        }
    } else {
        // ---------------- XG: Xg_t = seq_t @ Wih^T + bl (BN=64, weights resident) ----------------
        __half* Ws = smh;                         // [64][WSTRH_G]
        __half* As = smh + 64 * WSTRH_G;          // [2][128][ASTRH]
        const int n0 = (blockIdx.x - 64) * 64;

        for (int i = tid; i < 64 * 64; i += NTH) {
            const int r = i >> 6, c = (i & 63) * 8;
            *(uint4*)(Ws + r * WSTRH_G + c) = *(const uint4*)(g_Wihlh + (size_t)(n0 + r) * HH + c);
        }
        __syncthreads();

        for (int t = 0; t < TSTEPS; ++t) {
            if (t >= 1) wait_ge(&g_bar_gru, 64u * (unsigned)t);
            const __half* Abh = g_seqh + (size_t)t * BB * HH;

            float4 acc[2][4];
#pragma unroll
            for (int mi = 0; mi < 2; mi++)
#pragma unroll
                for (int ni = 0; ni < 4; ni++) acc[mi][ni] = make_float4(0.f, 0.f, 0.f, 0.f);

            uint4 pr[4];
#pragma unroll
            for (int i = 0; i < 4; i++)
                pr[i] = *(const uint4*)(Abh + (size_t)(rL + 32 * i) * HH + ch);
#pragma unroll
            for (int i = 0; i < 4; i++)
                *(uint4*)(As + (rL + 32 * i) * ASTRH + ch) = pr[i];
            __syncthreads();

            const int NK = HH / PBK;   // 8
            for (int kt = 0; kt < NK; ++kt) {
                const int  cur  = kt & 1;
                const bool more = (kt + 1 < NK);
                if (more) {
                    const int k0 = (kt + 1) * PBK;
#pragma unroll
                    for (int i = 0; i < 4; i++)
                        pr[i] = *(const uint4*)(Abh + (size_t)(rL + 32 * i) * HH + k0 + ch);
                }
                const __half* Ac = As + cur * BM * ASTRH;
#pragma unroll
                for (int kk = 0; kk < 4; kk++) {
                    const int kb = kk * 16 + 2 * (lane & 3);
                    const int kg = kt * PBK + kb;
                    uint32_t af[2][4];
#pragma unroll
                    for (int mi = 0; mi < 2; mi++) {
                        const __half* ap = Ac + (wm * 32 + mi * 16 + (lane >> 2)) * ASTRH + kb;
                        af[mi][0] = *(const uint32_t*)(ap);
                        af[mi][1] = *(const uint32_t*)(ap + 8 * ASTRH);
                        af[mi][2] = *(const uint32_t*)(ap + 8);
                        af[mi][3] = *(const uint32_t*)(ap + 8 * ASTRH + 8);
                    }
                    uint32_t bf[4][2];
#pragma unroll
                    for (int ni = 0; ni < 4; ni++) {
                        const __half* wp = Ws + (wn * 32 + ni * 8 + (lane >> 2)) * WSTRH_G + kg;
                        bf[ni][0] = *(const uint32_t*)(wp);
                        bf[ni][1] = *(const uint32_t*)(wp + 8);
                    }
#pragma unroll
                    for (int mi = 0; mi < 2; mi++)
#pragma unroll
                        for (int ni = 0; ni < 4; ni++)
                            mma_f16(acc[mi][ni], af[mi][0], af[mi][1], af[mi][2], af[mi][3],
                                    bf[ni][0], bf[ni][1]);
                }
                if (more) {
                    const int nxt = cur ^ 1;
#pragma unroll
                    for (int i = 0; i < 4; i++)
                        *(uint4*)(As + nxt * BM * ASTRH + (rL + 32 * i) * ASTRH + ch) = pr[i];
                }
                __syncthreads();
            }

            // direct epilogue: Xg = acc + bl
#pragma unroll
            for (int mi = 0; mi < 2; mi++) {
#pragma unroll
                for (int ni = 0; ni < 4; ni++) {
                    const int r   = wm * 32 + mi * 16 + (lane >> 2);
                    const int col = n0 + wn * 32 + ni * 8 + 2 * (lane & 3);
                    const float b0 = g_bl[col], b1 = g_bl[col + 1];
                    float* o0 = g_Xg + ((size_t)t * BB + r) * 4096 + col;
                    float* o1 = g_Xg + ((size_t)t * BB + r + 8) * 4096 + col;
                    *(float2*)o0 = make_float2(acc[mi][ni].x + b0, acc[mi][ni].y + b1);
                    *(float2*)o1 = make_float2(acc[mi][ni].z + b0, acc[mi][ni].w + b1);
                }
            }
            __syncthreads();
        }
    }
}

// ============================================================================
// FC work-steal worker: logits tile = hs_t @ fcW^T + fcb  (BM=128, BN=64, K=1024)
// ============================================================================
__device__ void fc_worker(__half* smh, const float* __restrict__ fcb,
                          float* __restrict__ out) {
    __shared__ int s_tile;
    __half* Bs = smh;                         // [2][64][ASTRH]
    __half* As = smh + 32 * WSTRH_L;          // [2][128][ASTRH]

    const int tid  = threadIdx.x;
    const int lane = tid & 31;
    const int wid  = tid >> 5;
    const int wm   = wid & 3;
    const int wn   = wid >> 2;
    const int rL   = tid >> 3;
    const int ch   = (tid & 7) * 8;

    while (true) {
        __syncthreads();
        if (tid == 0) s_tile = (int)atomicAdd(&g_fc_cnt, 1u);
        __syncthreads();
        const int tile = s_tile;
        if (tile >= TSTEPS * 16) return;
        const int t  = tile >> 4;
        const int n0 = (tile & 15) * 64;
        wait_ge(&g_bar_lstm, 128u * (unsigned)(t + 1));

        const __half* Abh = g_hsh  + (size_t)t * BB * LL;
        const __half* Wb  = g_fcWh + (size_t)n0 * LL;

        float4 acc[2][4];
#pragma unroll
        for (int mi = 0; mi < 2; mi++)
#pragma unroll
            for (int ni = 0; ni < 4; ni++) acc[mi][ni] = make_float4(0.f, 0.f, 0.f, 0.f);

        uint4 pr[4], qr[2];
#pragma unroll
        for (int i = 0; i < 4; i++)
            pr[i] = *(const uint4*)(Abh + (size_t)(rL + 32 * i) * LL + ch);
#pragma unroll
        for (int j = 0; j < 2; j++) {
            const int idx = tid + j * NTH;
            const int r = idx >> 3, c = (idx & 7) * 8;
            qr[j] = *(const uint4*)(Wb + (size_t)r * LL + c);
        }
#pragma unroll
        for (int i = 0; i < 4; i++)
            *(uint4*)(As + (rL + 32 * i) * ASTRH + ch) = pr[i];
#pragma unroll
        for (int j = 0; j < 2; j++) {
            const int idx = tid + j * NTH;
            const int r = idx >> 3, c = (idx & 7) * 8;
            *(uint4*)(Bs + r * ASTRH + c) = qr[j];
        }
        __syncthreads();

        const int NK = LL / PBK;   // 16
        for (int kt = 0; kt < NK; ++kt) {
            const int  cur  = kt & 1;
            const bool more = (kt + 1 < NK);
            if (more) {
                const int k0 = (kt + 1) * PBK;
#pragma unroll
                for (int i = 0; i < 4; i++)
                    pr[i] = *(const uint4*)(Abh + (size_t)(rL + 32 * i) * LL + k0 + ch);
#pragma unroll
                for (int j = 0; j < 2; j++) {
                    const int idx = tid + j * NTH;
                    const int r = idx >> 3, c = (idx & 7) * 8;
                    qr[j] = *(const uint4*)(Wb + (size_t)r * LL + k0 + c);
                }
            }
            const __half* Ac = As + cur * BM * ASTRH;
            const __half* Bc = Bs + cur * 64 * ASTRH;
#pragma unroll
            for (int kk = 0; kk < 4; kk++) {
                const int kb = kk * 16 + 2 * (lane & 3);
                uint32_t af[2][4];
#pragma unroll
                for (int mi = 0; mi < 2; mi++) {
                    const __half* ap = Ac + (wm * 32 + mi * 16 + (lane >> 2)) * ASTRH + kb;
                    af[mi][0] = *(const uint32_t*)(ap);
                    af[mi][1] = *(const uint32_t*)(ap + 8 * ASTRH);
                    af[mi][2] = *(const uint32_t*)(ap + 8);
                    af[mi][3] = *(const uint32_t*)(ap + 8 * ASTRH + 8);
                }
                uint32_t bf[4][2];
#pragma unroll
                for (int ni = 0; ni < 4; ni++) {
                    const __half* wp = Bc + (wn * 32 + ni * 8 + (lane >> 2)) * ASTRH + kb;
                    bf[ni][0] = *(const uint32_t*)(wp);
                    bf[ni][1] = *(const uint32_t*)(wp + 8);
                }
#pragma unroll
                for (int mi = 0; mi < 2; mi++)
#pragma unroll
                    for (int ni = 0; ni < 4; ni++)
                        mma_f16(acc[mi][ni], af[mi][0], af[mi][1], af[mi][2], af[mi][3],
                                bf[ni][0], bf[ni][1]);
            }
            if (more) {
                const int nxt = cur ^ 1;
#pragma unroll
                for (int i = 0; i < 4; i++)
                    *(uint4*)(As + nxt * BM * ASTRH + (rL + 32 * i) * ASTRH + ch) = pr[i];
#pragma unroll
                for (int j = 0; j < 2; j++) {
                    const int idx = tid + j * NTH;
                    const int r = idx >> 3, c = (idx & 7) * 8;
                    *(uint4*)(Bs + nxt * 64 * ASTRH + r * ASTRH + c) = qr[j];
                }
            }
            __syncthreads();
        }

        // direct epilogue: out[(b*T + t)*V + col]  (b = tile row)
#pragma unroll
        for (int mi = 0; mi < 2; mi++) {
#pragma unroll
            for (int ni = 0; ni < 4; ni++) {
                const int r   = wm * 32 + mi * 16 + (lane >> 2);
                const int col = n0 + wn * 32 + ni * 8 + 2 * (lane & 3);
                const float b0 = fcb[col], b1 = fcb[col + 1];
                float* o0 = out + ((size_t)r * TSTEPS + t) * VV + col;
                float* o1 = out + ((size_t)(r + 8) * TSTEPS + t) * VV + col;
                *(float2*)o0 = make_float2(acc[mi][ni].x + b0, acc[mi][ni].y + b1);
                *(float2*)o1 = make_float2(acc[mi][ni].z + b0, acc[mi][ni].w + b1);
            }
        }
    }
}

// ============================================================================
// Kernel B: grid 148.  CTAs 0-127: LSTM chain, then join FC steal.
//                      CTAs 128-147: FC work-steal from the start.
// ============================================================================
__global__ void __launch_bounds__(NTH)
lstmfc_persist(const float* __restrict__ fcb, float* __restrict__ out) {
    extern __shared__ __half smh[];
    const int tid  = threadIdx.x;
    const int lane = tid & 31;
    const int wid  = tid >> 5;
    const int wm   = wid & 3;
    const int wn   = wid >> 2;
    const int rL   = tid >> 3;
    const int ch   = (tid & 7) * 8;

    if (blockIdx.x < 128) {
        __half* Ws = smh;                         // [32][WSTRH_L]
        __half* As = smh + 32 * WSTRH_L;          // [2][128][ASTRH]
        float*  Cs = (float*)As;
        const int n0 = blockIdx.x * PBN;

        for (int i = tid; i < 32 * 128; i += NTH) {
            const int r = i >> 7, c = (i & 127) * 8;
            *(uint4*)(Ws + r * WSTRH_L + c) = *(const uint4*)(g_Whhlh + (size_t)(n0 + r) * LL + c);
        }
        __syncthreads();

        for (int t = 0; t < TSTEPS; ++t) {
            const __half* Abh = g_hh + (size_t)(t & 1) * BB * LL;
            __half* hoh       = g_hh + (size_t)((t + 1) & 1) * BB * LL;

            float4 xg[4];
            float  cc[4];
#pragma unroll
            for (int r = 0; r < 4; r++) {
                const int row = rL + 32 * r;
                const int u   = tid & 7;
                xg[r] = *(const float4*)(g_Xg + ((size_t)t * BB + row) * 4096 + n0 + 4 * u);
                cc[r] = g_c[row * LL + (n0 >> 2) + u];
            }

            float4 acc[2][2];
#pragma unroll
            for (int mi = 0; mi < 2; mi++)
#pragma unroll
                for (int ni = 0; ni < 2; ni++) acc[mi][ni] = make_float4(0.f, 0.f, 0.f, 0.f);

            uint4 pr[4];
#pragma unroll
            for (int i = 0; i < 4; i++)
                pr[i] = *(const uint4*)(Abh + (size_t)(rL + 32 * i) * LL + ch);
#pragma unroll
            for (int i = 0; i < 4; i++)
                *(uint4*)(As + (rL + 32 * i) * ASTRH + ch) = pr[i];
            __syncthreads();

            const int NK = LL / PBK;   // 16
            for (int kt = 0; kt < NK; ++kt) {
                const int  cur  = kt & 1;
                const bool more = (kt + 1 < NK);
                if (more) {
                    const int k0 = (kt + 1) * PBK;
#pragma unroll
                    for (int i = 0; i < 4; i++)
                        pr[i] = *(const uint4*)(Abh + (size_t)(rL + 32 * i) * LL + k0 + ch);
                }
                const __half* Ac = As + cur * BM * ASTRH;
#pragma unroll
                for (int kk = 0; kk < 4; kk++) {
                    const int kb = kk * 16 + 2 * (lane & 3);
                    const int kg = kt * PBK + kb;
                    uint32_t af[2][4];
#pragma unroll
                    for (int mi = 0; mi < 2; mi++) {
                        const __half* ap = Ac + (wm * 32 + mi * 16 + (lane >> 2)) * ASTRH + kb;
                        af[mi][0] = *(const uint32_t*)(ap);
                        af[mi][1] = *(const uint32_t*)(ap + 8 * ASTRH);
                        af[mi][2] = *(const uint32_t*)(ap + 8);
                        af[mi][3] = *(const uint32_t*)(ap + 8 * ASTRH + 8);
                    }
                    uint32_t bf[2][2];
#pragma unroll
                    for (int ni = 0; ni < 2; ni++) {
                        const __half* wp = Ws + (wn * 16 + ni * 8 + (lane >> 2)) * WSTRH_L + kg;
                        bf[ni][0] = *(const uint32_t*)(wp);
                        bf[ni][1] = *(const uint32_t*)(wp + 8);
                    }
#pragma unroll
                    for (int mi = 0; mi < 2; mi++)
#pragma unroll
                        for (int ni = 0; ni < 2; ni++)
                            mma_f16(acc[mi][ni], af[mi][0], af[mi][1], af[mi][2], af[mi][3],
                                    bf[ni][0], bf[ni][1]);
                }
                if (more) {
                    const int nxt = cur ^ 1;
#pragma unroll
                    for (int i = 0; i < 4; i++)
                        *(uint4*)(As + nxt * BM * ASTRH + (rL + 32 * i) * ASTRH + ch) = pr[i];
                }
                __syncthreads();
            }

#pragma unroll
            for (int mi = 0; mi < 2; mi++) {
#pragma unroll
                for (int ni = 0; ni < 2; ni++) {
                    const int r = wm * 32 + mi * 16 + (lane >> 2);
                    const int c = wn * 16 + ni * 8 + 2 * (lane & 3);
                    Cs[r * PCSTR + c]           = acc[mi][ni].x;
                    Cs[r * PCSTR + c + 1]       = acc[mi][ni].y;
                    Cs[(r + 8) * PCSTR + c]     = acc[mi][ni].z;
                    Cs[(r + 8) * PCSTR + c + 1] = acc[mi][ni].w;
                }
            }
            __syncthreads();

#pragma unroll
            for (int r = 0; r < 4; r++) {
                const int row = rL + 32 * r;
                const int u   = tid & 7;
                const int jg  = (n0 >> 2) + u;
                const float4 cv = *(const float4*)(Cs + row * PCSTR + 4 * u);
                const float ig = sigf(cv.x + xg[r].x);
                const float fg = sigf(cv.y + xg[r].y);
                const float gg = tanhf(cv.z + xg[r].z);
                const float og = sigf(cv.w + xg[r].w);
                const int ci = row * LL + jg;
                const float cn = fg * cc[r] + ig * gg;
                g_c[ci] = cn;
                const float hn = og * tanhf(cn);
                hoh[ci] = __float2half_rn(hn);
                g_hsh[((size_t)t * BB + row) * LL + jg] = __float2half_rn(hn);
            }

            bar_arrive(&g_bar_lstm);
            if (t < TSTEPS - 1)
                wait_ge(&g_bar_lstm, 128u * (unsigned)(t + 1));
        }
        // chain done -> help FC
        fc_worker(smh, fcb, out);
    } else {
        fc_worker(smh, fcb, out);
    }
}

// ---------------- prep kernels ----------------
__global__ void prep_gru(const float* __restrict__ Wih, const float* __restrict__ Whh,
                         const float* __restrict__ bih, const float* __restrict__ bhh) {
    const int idx = blockIdx.x * blockDim.x + threadIdx.x;
    if (idx < 2048 * 512) {
        const int row = idx >> 9, k = idx & 511;
        const int j = row >> 2, g = row & 3;
        float wg, w1;
        if (g == 0)      { wg = Wih[j * 512 + k] + Whh[j * 512 + k];                 w1 = Whh[j * 512 + k]; }
        else if (g == 1) { wg = Wih[(512 + j) * 512 + k] + Whh[(512 + j) * 512 + k]; w1 = Whh[(512 + j) * 512 + k]; }
        else if (g == 2) { wg = Wih[(1024 + j) * 512 + k];                           w1 = 0.f; }
        else             { wg = Whh[(1024 + j) * 512 + k];                           w1 = wg; }
        g_Wgh[idx]  = __float2half_rn(wg);
        g_Wg1h[idx] = __float2half_rn(w1);
    }
    if (idx < 2048) {
        const int j = idx >> 2, g = idx & 3;
        float b;
        if (g == 0)      b = bih[j] + bhh[j];
        else if (g == 1) b = bih[512 + j] + bhh[512 + j];
        else if (g == 2) b = bih[1024 + j];
        else             b = bhh[1024 + j];
        g_bg[idx] = b;
    }
}

__global__ void prep_lstm(const float* __restrict__ Wih, const float* __restrict__ Whh,
                          const float* __restrict__ bih, const float* __restrict__ bhh,
                          const float* __restrict__ fcW) {
    const int idx = blockIdx.x * blockDim.x + threadIdx.x;
    if (idx < 4096 * 1024) {
        const int row = idx >> 10, k = idx & 1023;
        const int j = row >> 2, p = row & 3;
        g_Whhlh[idx] = __float2half_rn(Whh[(size_t)(p * 1024 + j) * 1024 + k]);
    }
    if (idx < 4096 * 512) {
        const int row = idx >> 9, k = idx & 511;
        const int j = row >> 2, p = row & 3;
        g_Wihlh[idx] = __float2half_rn(Wih[(size_t)(p * 1024 + j) * 512 + k]);
    }
    if (idx < 1024 * 1024) {
        g_fcWh[idx] = __float2half_rn(fcW[idx]);
    }
    if (idx < 4096) {
        const int j = idx >> 2, p = idx & 3;
        g_bl[idx] = bih[p * 1024 + j] + bhh[p * 1024 + j];
    }
}

__global__ void prep_zero(const float* __restrict__ z) {
    const int idx = blockIdx.x * blockDim.x + threadIdx.x;
    if (idx < BB * LL) { g_hh[idx] = __float2half_rn(0.f); g_c[idx] = 0.f; }
    if (idx < BB * HH) { g_zh[idx] = __float2half_rn(z[idx]); g_seqh[idx] = __float2half_rn(0.f); }
    if (idx == 0) { g_bar_gru = 0u; g_bar_lstm = 0u; g_fc_cnt = 0u; }
}

// ---------------- host launcher ----------------
extern "C" void kernel_launch(void* const* d_in, const int* in_sizes, int n_in,
                              void* d_out, int out_size) {
    const float* z    = (const float*)d_in[0];
    const float* gWih = (const float*)d_in[2];
    const float* gWhh = (const float*)d_in[3];
    const float* gbih = (const float*)d_in[4];
    const float* gbhh = (const float*)d_in[5];
    const float* lWih = (const float*)d_in[6];
    const float* lWhh = (const float*)d_in[7];
    const float* lbih = (const float*)d_in[8];
    const float* lbhh = (const float*)d_in[9];
    const float* fcW  = (const float*)d_in[10];
    const float* fcb  = (const float*)d_in[11];
    float* out = (float*)d_out;

    cudaFuncSetAttribute(gruxg_persist,  cudaFuncAttributeMaxDynamicSharedMemorySize, SMEM_A_KERN);
    cudaFuncSetAttribute(lstmfc_persist, cudaFuncAttributeMaxDynamicSharedMemorySize, SMEM_B_KERN);

    prep_gru <<<(2048 * 512 + 255) / 256, 256>>>(gWih, gWhh, gbih, gbhh);
    prep_lstm<<<(4096 * 1024 + 255) / 256, 256>>>(lWih, lWhh, lbih, lbhh, fcW);
    prep_zero<<<(BB * LL + 255) / 256, 256>>>(z);

    // Kernel A: GRU chain (64 CTAs) + overlapped XG (64 CTAs)
    gruxg_persist<<<128, NTH, SMEM_A_KERN>>>(z);

    // Kernel B: LSTM chain (128 CTAs) + FC work-steal (20 CTAs + post-chain join)
    lstmfc_persist<<<148, NTH, SMEM_B_KERN>>>(fcb, out);
}